// round 2
// baseline (speedup 1.0000x reference)
#include <cuda_runtime.h>
#include <cuda_bf16.h>
#include <math.h>

#define S_LEN 1024
#define D_MODEL 1024
#define NH 16
#define DH 64
#define L_LAYERS 4
#define DFF 4096
#define TPF 8
#define NFRAMES (S_LEN / TPF)

// ---------------- scratch (device globals; no allocation) ----------------
__device__ float g_h[S_LEN * D_MODEL];          // 4 MB
__device__ float g_qkv[S_LEN * 3 * D_MODEL];    // 12 MB
__device__ float g_attno[S_LEN * D_MODEL];      // 4 MB
__device__ float g_ff[S_LEN * DFF];             // 16 MB
__device__ float g_mod[L_LAYERS * 6 * D_MODEL]; // [shift1|scale1|gate1|shift2|scale2|gate2] per layer

// ---------------- mod/gate precompute (depends only on cond) ----------------
__global__ void modgate_kernel(const float* __restrict__ cond,
                               const float* __restrict__ a1w, const float* __restrict__ a1b,
                               const float* __restrict__ g1w, const float* __restrict__ g1b,
                               const float* __restrict__ a2w, const float* __restrict__ a2b,
                               const float* __restrict__ g2w, const float* __restrict__ g2b,
                               float* __restrict__ out) {
    __shared__ float cs[D_MODEL];
    for (int i = threadIdx.x; i < D_MODEL; i += blockDim.x) cs[i] = cond[i];
    __syncthreads();
    int o = blockIdx.x * blockDim.x + threadIdx.x;   // global output index
    int l = o / (6 * D_MODEL);
    int j = o % (6 * D_MODEL);
    const float* W; const float* Bv; int col, ncols;
    if (j < 2 * D_MODEL)      { W = a1w + (size_t)l * D_MODEL * 2 * D_MODEL; Bv = a1b + l * 2 * D_MODEL; col = j;                ncols = 2 * D_MODEL; }
    else if (j < 3 * D_MODEL) { W = g1w + (size_t)l * D_MODEL * D_MODEL;     Bv = g1b + l * D_MODEL;     col = j - 2 * D_MODEL;  ncols = D_MODEL; }
    else if (j < 5 * D_MODEL) { W = a2w + (size_t)l * D_MODEL * 2 * D_MODEL; Bv = a2b + l * 2 * D_MODEL; col = j - 3 * D_MODEL;  ncols = 2 * D_MODEL; }
    else                      { W = g2w + (size_t)l * D_MODEL * D_MODEL;     Bv = g2b + l * D_MODEL;     col = j - 5 * D_MODEL;  ncols = D_MODEL; }
    float acc = 0.f;
    #pragma unroll 8
    for (int d = 0; d < D_MODEL; d++) acc += cs[d] * W[(size_t)d * ncols + col];
    out[o] = acc + Bv[col];
}

// ---------------- LayerNorm + adaLN modulation ----------------
__global__ void ln_mod_kernel(const float* __restrict__ x,
                              const float* __restrict__ shift,
                              const float* __restrict__ scale,
                              float* __restrict__ h) {
    int row = blockIdx.x;
    int tid = threadIdx.x;               // 256
    const float* xr = x + (size_t)row * D_MODEL;
    float v[4], s = 0.f, s2 = 0.f;
    #pragma unroll
    for (int i = 0; i < 4; i++) {
        v[i] = xr[tid + i * 256];
        s += v[i]; s2 += v[i] * v[i];
    }
    #pragma unroll
    for (int off = 16; off; off >>= 1) {
        s  += __shfl_xor_sync(0xffffffff, s,  off);
        s2 += __shfl_xor_sync(0xffffffff, s2, off);
    }
    __shared__ float sh1[8], sh2[8];
    int w = tid >> 5, lane = tid & 31;
    if (lane == 0) { sh1[w] = s; sh2[w] = s2; }
    __syncthreads();
    if (tid == 0) {
        float a = 0.f, b = 0.f;
        #pragma unroll
        for (int i = 0; i < 8; i++) { a += sh1[i]; b += sh2[i]; }
        sh1[0] = a; sh2[0] = b;
    }
    __syncthreads();
    float mean = sh1[0] * (1.f / D_MODEL);
    float var  = sh2[0] * (1.f / D_MODEL) - mean * mean;
    float r = rsqrtf(var + 1e-5f);
    float* hr = h + (size_t)row * D_MODEL;
    #pragma unroll
    for (int i = 0; i < 4; i++) {
        int col = tid + i * 256;
        hr[col] = (v[i] - mean) * r * (1.f + scale[col]) + shift[col];
    }
}

// ---------------- SGEMM: C = A[MxK] @ W[KxN] + bias, fused epilogues ----------------
// MODE 0: C = acc + bias
// MODE 1: C = gelu_tanh(acc + bias)
// MODE 2: C = X + (acc + bias) * gate  (residual-gated; C==X allowed)
__device__ __forceinline__ float gelu_tanh(float v) {
    float t = tanhf(0.7978845608028654f * (v + 0.044715f * v * v * v));
    return 0.5f * v * (1.f + t);
}

template <int MODE>
__global__ void __launch_bounds__(256, 2)
gemm_kernel(const float* __restrict__ A, const float* __restrict__ W,
            const float* __restrict__ bias, const float* __restrict__ gate,
            float* __restrict__ C, const float* __restrict__ X,
            int M, int N, int K) {
    __shared__ float As[8][132];
    __shared__ float Bs[8][132];
    int bm = blockIdx.y * 128, bn = blockIdx.x * 128;
    int tid = threadIdx.x;
    int tx = tid & 15, ty = tid >> 4;
    float acc[8][8];
    #pragma unroll
    for (int i = 0; i < 8; i++)
        #pragma unroll
        for (int j = 0; j < 8; j++) acc[i][j] = 0.f;

    for (int k0 = 0; k0 < K; k0 += 8) {
        #pragma unroll
        for (int i = 0; i < 4; i++) {
            int idx = tid + i * 256;
            int r = idx >> 3, c = idx & 7;
            As[c][r] = A[(size_t)(bm + r) * K + k0 + c];
        }
        #pragma unroll
        for (int i = 0; i < 4; i++) {
            int idx = tid + i * 256;
            int r = idx >> 7, c = idx & 127;
            Bs[r][c] = W[(size_t)(k0 + r) * N + bn + c];
        }
        __syncthreads();
        #pragma unroll
        for (int k = 0; k < 8; k++) {
            float a[8], b[8];
            #pragma unroll
            for (int i = 0; i < 8; i++) a[i] = As[k][ty * 8 + i];
            #pragma unroll
            for (int j = 0; j < 8; j++) b[j] = Bs[k][tx * 8 + j];
            #pragma unroll
            for (int i = 0; i < 8; i++)
                #pragma unroll
                for (int j = 0; j < 8; j++)
                    acc[i][j] = fmaf(a[i], b[j], acc[i][j]);
        }
        __syncthreads();
    }

    #pragma unroll
    for (int i = 0; i < 8; i++) {
        int row = bm + ty * 8 + i;
        #pragma unroll
        for (int j = 0; j < 8; j++) {
            int col = bn + tx * 8 + j;
            float v = acc[i][j] + bias[col];
            if (MODE == 1) v = gelu_tanh(v);
            if (MODE == 2) v = X[(size_t)row * N + col] + v * gate[col];
            C[(size_t)row * N + col] = v;
        }
    }
}

// ---------------- per-(token, head) RMSNorm + RoPE on Q and K ----------------
__global__ void rmsrope_kernel(float* __restrict__ qkv) {
    int s = blockIdx.x;
    int hh = blockIdx.y;          // 0..31
    int which = hh >> 4;          // 0=q, 1=k
    int h = hh & 15;
    int lane = threadIdx.x;       // 32
    float* base = qkv + (size_t)s * 3 * D_MODEL + which * D_MODEL + h * DH;
    float x1 = base[lane], x2 = base[lane + 32];
    float ss = x1 * x1 + x2 * x2;
    #pragma unroll
    for (int off = 16; off; off >>= 1) ss += __shfl_xor_sync(0xffffffff, ss, off);
    float r = rsqrtf(ss * (1.f / DH) + 1e-6f);
    x1 *= r; x2 *= r;
    // angles in double for robustness; reference is fp32 so this strictly tightens error
    double inv = exp(-((double)lane / 32.0) * 9.210340371976184);  // ln(10000)
    double ang = (double)s * inv;
    float c = (float)cos(ang), sn = (float)sin(ang);
    base[lane]      = x1 * c - x2 * sn;
    base[lane + 32] = x1 * sn + x2 * c;
}

// ---------------- frame-masked flash attention ----------------
// grid: (NFRAMES, NH), block 256.  warp w handles query row w of the 8-token frame.
__global__ void __launch_bounds__(256, 4)
attn_kernel(const float* __restrict__ qkv, float* __restrict__ O, int window) {
    int f = blockIdx.x;
    int h = blockIdx.y;
    int tid = threadIdx.x;
    int warp = tid >> 5, lane = tid & 31;
    __shared__ float Qs[8][DH];
    __shared__ float Ks[32][DH + 4];
    __shared__ float Vs[32][DH + 2];
    int h0 = h * DH;
    int qrow0 = f * TPF;
    for (int i = tid; i < 8 * DH; i += 256) {
        int r = i >> 6, d = i & 63;
        Qs[r][d] = qkv[(size_t)(qrow0 + r) * 3 * D_MODEL + h0 + d];
    }
    __syncthreads();

    int fstart = max(0, f - window + 1);
    int kstart = fstart * TPF;
    int kend = (f + 1) * TPF;
    int nk = kend - kstart;

    float m = -1e30f, l = 0.f;
    float o0 = 0.f, o1 = 0.f;
    int q = warp;
    int d0 = lane * 2;
    const float sc = 0.125f;  // 1/sqrt(64)

    for (int c0 = 0; c0 < nk; c0 += 32) {
        for (int i = tid; i < 32 * DH; i += 256) {
            int r = i >> 6, d = i & 63;
            int kr = kstart + c0 + r;
            if (kr > S_LEN - 1) kr = S_LEN - 1;
            Ks[r][d] = qkv[(size_t)kr * 3 * D_MODEL + D_MODEL + h0 + d];
            Vs[r][d] = qkv[(size_t)kr * 3 * D_MODEL + 2 * D_MODEL + h0 + d];
        }
        __syncthreads();

        float s;
        if (c0 + lane < nk) {
            float a0 = 0.f, a1 = 0.f, a2 = 0.f, a3 = 0.f;
            #pragma unroll
            for (int d = 0; d < DH; d += 4) {
                a0 = fmaf(Qs[q][d],     Ks[lane][d],     a0);
                a1 = fmaf(Qs[q][d + 1], Ks[lane][d + 1], a1);
                a2 = fmaf(Qs[q][d + 2], Ks[lane][d + 2], a2);
                a3 = fmaf(Qs[q][d + 3], Ks[lane][d + 3], a3);
            }
            s = (a0 + a1 + a2 + a3) * sc;
        } else {
            s = -1e30f;
        }
        float cm = s;
        #pragma unroll
        for (int off = 16; off; off >>= 1) cm = fmaxf(cm, __shfl_xor_sync(0xffffffff, cm, off));
        float mnew = fmaxf(m, cm);
        float p = __expf(s - mnew);
        if (c0 + lane >= nk) p = 0.f;
        float ps = p;
        #pragma unroll
        for (int off = 16; off; off >>= 1) ps += __shfl_xor_sync(0xffffffff, ps, off);
        float factor = __expf(m - mnew);
        l = l * factor + ps;
        m = mnew;
        o0 *= factor; o1 *= factor;
        #pragma unroll
        for (int k = 0; k < 32; k++) {
            float pk = __shfl_sync(0xffffffff, p, k);
            o0 = fmaf(pk, Vs[k][d0],     o0);
            o1 = fmaf(pk, Vs[k][d0 + 1], o1);
        }
        __syncthreads();
    }
    float invl = 1.f / l;
    O[(size_t)(qrow0 + q) * D_MODEL + h0 + d0]     = o0 * invl;
    O[(size_t)(qrow0 + q) * D_MODEL + h0 + d0 + 1] = o1 * invl;
}

// ---------------- host-side orchestration ----------------
extern "C" void kernel_launch(void* const* d_in, const int* in_sizes, int n_in,
                              void* d_out, int out_size) {
    const float* x       = (const float*)d_in[0];
    const float* cond    = (const float*)d_in[1];
    const float* qkv_w   = (const float*)d_in[2];
    const float* qkv_b   = (const float*)d_in[3];
    const float* out_w   = (const float*)d_in[4];
    const float* out_b   = (const float*)d_in[5];
    const float* mlp_w1  = (const float*)d_in[6];
    const float* mlp_b1  = (const float*)d_in[7];
    const float* mlp_w2  = (const float*)d_in[8];
    const float* mlp_b2  = (const float*)d_in[9];
    const float* ada1_w  = (const float*)d_in[10];
    const float* ada1_b  = (const float*)d_in[11];
    const float* gate1_w = (const float*)d_in[12];
    const float* gate1_b = (const float*)d_in[13];
    const float* ada2_w  = (const float*)d_in[14];
    const float* ada2_b  = (const float*)d_in[15];
    const float* gate2_w = (const float*)d_in[16];
    const float* gate2_b = (const float*)d_in[17];
    float* X = (float*)d_out;

    float *h_ptr, *qkv_ptr, *attno_ptr, *ff_ptr, *mod_ptr;
    cudaGetSymbolAddress((void**)&h_ptr,     g_h);
    cudaGetSymbolAddress((void**)&qkv_ptr,   g_qkv);
    cudaGetSymbolAddress((void**)&attno_ptr, g_attno);
    cudaGetSymbolAddress((void**)&ff_ptr,    g_ff);
    cudaGetSymbolAddress((void**)&mod_ptr,   g_mod);

    cudaMemcpyAsync(X, x, (size_t)S_LEN * D_MODEL * sizeof(float), cudaMemcpyDeviceToDevice);

    modgate_kernel<<<L_LAYERS * 6 * D_MODEL / 256, 256>>>(
        cond, ada1_w, ada1_b, gate1_w, gate1_b, ada2_w, ada2_b, gate2_w, gate2_b, mod_ptr);

    for (int i = 0; i < L_LAYERS; i++) {
        const float* mod = mod_ptr + i * 6 * D_MODEL;
        int window = (i % 4 == 0) ? 128 : 8;

        // h = LN(x)*(1+scale1)+shift1
        ln_mod_kernel<<<S_LEN, 256>>>(X, mod, mod + D_MODEL, h_ptr);

        // qkv = h @ qkv_w + qkv_b
        gemm_kernel<0><<<dim3(3 * D_MODEL / 128, S_LEN / 128), 256>>>(
            h_ptr, qkv_w + (size_t)i * D_MODEL * 3 * D_MODEL, qkv_b + i * 3 * D_MODEL,
            nullptr, qkv_ptr, nullptr, S_LEN, 3 * D_MODEL, D_MODEL);

        // per-head RMSNorm + RoPE on q,k (in place)
        rmsrope_kernel<<<dim3(S_LEN, 2 * NH), 32>>>(qkv_ptr);

        // attention with frame mask
        attn_kernel<<<dim3(NFRAMES, NH), 256>>>(qkv_ptr, attno_ptr, window);

        // x = x + (attno @ out_w + out_b) * gate1
        gemm_kernel<2><<<dim3(D_MODEL / 128, S_LEN / 128), 256>>>(
            attno_ptr, out_w + (size_t)i * D_MODEL * D_MODEL, out_b + i * D_MODEL,
            mod + 2 * D_MODEL, X, X, S_LEN, D_MODEL, D_MODEL);

        // h = LN(x)*(1+scale2)+shift2
        ln_mod_kernel<<<S_LEN, 256>>>(X, mod + 3 * D_MODEL, mod + 4 * D_MODEL, h_ptr);

        // ff = gelu(h @ mlp_w1 + b1)
        gemm_kernel<1><<<dim3(DFF / 128, S_LEN / 128), 256>>>(
            h_ptr, mlp_w1 + (size_t)i * D_MODEL * DFF, mlp_b1 + i * DFF,
            nullptr, ff_ptr, nullptr, S_LEN, DFF, D_MODEL);

        // x = x + (ff @ mlp_w2 + b2) * gate2
        gemm_kernel<2><<<dim3(D_MODEL / 128, S_LEN / 128), 256>>>(
            ff_ptr, mlp_w2 + (size_t)i * DFF * D_MODEL, mlp_b2 + i * D_MODEL,
            mod + 5 * D_MODEL, X, X, S_LEN, D_MODEL, DFF);
    }
}

// round 5
// speedup vs baseline: 3.0625x; 3.0625x over previous
#include <cuda_runtime.h>
#include <cuda_bf16.h>
#include <math.h>
#include <stdint.h>

#define S_LEN 1024
#define D_MODEL 1024
#define NH 16
#define DH 64
#define L_LAYERS 4
#define DFF 4096
#define TPF 8
#define NFRAMES (S_LEN / TPF)

// ---------------- scratch (device globals; no allocation) ----------------
__device__ float g_h[S_LEN * D_MODEL];
__device__ float g_qkv[S_LEN * 3 * D_MODEL];
__device__ float g_attno[S_LEN * D_MODEL];
__device__ float g_ff[S_LEN * DFF];
__device__ float g_mod[L_LAYERS * 6 * D_MODEL];
__device__ float g_ropec[S_LEN * 32];
__device__ float g_ropes[S_LEN * 32];
// split bf16 operands: A' [M, 3K] (max 1024 x 12288), B'^T [N, 3K]
__device__ __nv_bfloat16 g_abuf[1024 * 12288];
__device__ __nv_bfloat16 g_wbuf[4096 * 3072 > 1024 * 12288 ? 4096 * 3072 : 1024 * 12288];

// ---------------- helpers ----------------
__device__ __forceinline__ uint32_t smem_u32(const void* p) {
    uint32_t a;
    asm("{ .reg .u64 t; cvta.to.shared.u64 t, %1; cvt.u32.u64 %0, t; }" : "=r"(a) : "l"(p));
    return a;
}
#define CP16(dst, src) \
    asm volatile("cp.async.cg.shared.global [%0], [%1], 16;" :: "r"(dst), "l"(src))
#define CP_COMMIT() asm volatile("cp.async.commit_group;")
#define CP_WAIT(n)  asm volatile("cp.async.wait_group %0;" :: "n"(n))
#define LDSM4(r0, r1, r2, r3, addr)                                        \
    asm volatile("ldmatrix.sync.aligned.m8n8.x4.shared.b16 {%0,%1,%2,%3}, [%4];" \
        : "=r"(r0), "=r"(r1), "=r"(r2), "=r"(r3) : "r"(addr))

__device__ __forceinline__ float gelu_tanh(float v) {
    float t = tanhf(0.7978845608028654f * (v + 0.044715f * v * v * v));
    return 0.5f * v * (1.f + t);
}

// ---------------- split conversion kernels ----------------
// activations: in [M,K] fp32 -> out [M, 3K] bf16: [hi | lo | hi]
__global__ void split_act_kernel(const float* __restrict__ in,
                                 __nv_bfloat16* __restrict__ out, int kbits) {
    int idx = blockIdx.x * 256 + threadIdx.x;
    int K = 1 << kbits;
    int m = idx >> kbits, k = idx & (K - 1);
    float a = in[idx];
    __nv_bfloat16 hi = __float2bfloat16(a);
    __nv_bfloat16 lo = __float2bfloat16(a - __bfloat162float(hi));
    size_t base = (size_t)m * (3 * K) + k;
    out[base]         = hi;
    out[base + K]     = lo;
    out[base + 2 * K] = hi;
}

// weights: W [K,N] fp32 -> out [N, 3K] bf16 transposed: [hi | hi | lo]
__global__ void split_wT_kernel(const float* __restrict__ W,
                                __nv_bfloat16* __restrict__ out, int K, int N) {
    __shared__ float t[32][33];
    int n0 = blockIdx.x * 32, k0 = blockIdx.y * 32;
    int tx = threadIdx.x, ty = threadIdx.y;  // (32, 8)
    #pragma unroll
    for (int i = 0; i < 32; i += 8)
        t[ty + i][tx] = W[(size_t)(k0 + ty + i) * N + n0 + tx];
    __syncthreads();
    #pragma unroll
    for (int i = 0; i < 32; i += 8) {
        float a = t[tx][ty + i];
        __nv_bfloat16 hi = __float2bfloat16(a);
        __nv_bfloat16 lo = __float2bfloat16(a - __bfloat162float(hi));
        size_t row = (size_t)(n0 + ty + i) * (3 * K);
        out[row + k0 + tx]         = hi;
        out[row + K + k0 + tx]     = hi;
        out[row + 2 * K + k0 + tx] = lo;
    }
}

// ---------------- mma.sync bf16 GEMM: C[M,N] = A'[M,KK] . B'[N,KK]^T ----------------
// MODE 0: C = acc + bias ; MODE 1: C = gelu(acc + bias) ; MODE 2: C = X + (acc+bias)*gate
// BM in {128, 64}; BN = 128; BK = 32; 8 warps; 3-stage cp.async pipeline.
template <int MODE, int BM>
__global__ void __launch_bounds__(256, 2)
mma_gemm(const __nv_bfloat16* __restrict__ A, const __nv_bfloat16* __restrict__ B,
         const float* __restrict__ bias, const float* __restrict__ gate,
         float* __restrict__ C, const float* __restrict__ X,
         int M, int N, int KK) {
    constexpr int WARPS_M = BM / 32;
    constexpr int WARPS_N = 8 / WARPS_M;
    constexpr int WTN = 128 / WARPS_N;   // 64 or 32
    constexpr int NAT = WTN / 8;         // 8 or 4
    constexpr int STAGES = 3;
    constexpr int ROWB = 80;             // padded row stride bytes (32 bf16 + 8 pad)
    constexpr int STG_A = BM * ROWB;
    constexpr int STG_B = 128 * ROWB;
    constexpr int STG = STG_A + STG_B;
    constexpr int A_OPS = BM * 4 / 256;  // 16B ops per thread for A
    constexpr int B_OPS = 2;

    extern __shared__ __align__(128) char dyn[];
    uint32_t sb = smem_u32(dyn);
    int tid = threadIdx.x;
    int wid = tid >> 5, lane = tid & 31;
    int wm = wid / WARPS_N, wn = wid % WARPS_N;
    int bm = blockIdx.y * BM, bn = blockIdx.x * 128;

    float acc[2][NAT][4];
    #pragma unroll
    for (int i = 0; i < 2; i++)
        #pragma unroll
        for (int j = 0; j < NAT; j++)
            #pragma unroll
            for (int q = 0; q < 4; q++) acc[i][j][q] = 0.f;

    // global src base offsets per thread
    const __nv_bfloat16* srcA[A_OPS];
    uint32_t dstA[A_OPS];
    #pragma unroll
    for (int i = 0; i < A_OPS; i++) {
        int idx = tid + i * 256;
        int r = idx >> 2, seg = idx & 3;
        srcA[i] = A + (size_t)(bm + r) * KK + seg * 8;
        dstA[i] = sb + r * ROWB + seg * 16;
    }
    const __nv_bfloat16* srcB[B_OPS];
    uint32_t dstB[B_OPS];
    #pragma unroll
    for (int i = 0; i < B_OPS; i++) {
        int idx = tid + i * 256;
        int r = idx >> 2, seg = idx & 3;
        srcB[i] = B + (size_t)(bn + r) * KK + seg * 8;
        dstB[i] = sb + STG_A + r * ROWB + seg * 16;
    }

    int nch = KK >> 5;

    // prologue: stages 0..STAGES-2
    #pragma unroll
    for (int s = 0; s < STAGES - 1; s++) {
        #pragma unroll
        for (int i = 0; i < A_OPS; i++) CP16(dstA[i] + s * STG, srcA[i] + s * 32);
        #pragma unroll
        for (int i = 0; i < B_OPS; i++) CP16(dstB[i] + s * STG, srcB[i] + s * 32);
        CP_COMMIT();
    }

    // ldmatrix lane-address offsets (relative to stage base)
    int grp = lane >> 3, lr = lane & 7;
    // A: row = wm*32 + ma*16 + (grp&1)*8 + lr ; koff = ks*16 + (grp>>1)*8
    uint32_t aoff[2][2];
    #pragma unroll
    for (int ks = 0; ks < 2; ks++)
        #pragma unroll
        for (int ma = 0; ma < 2; ma++)
            aoff[ks][ma] = (wm * 32 + ma * 16 + (grp & 1) * 8 + lr) * ROWB +
                           (ks * 16 + (grp >> 1) * 8) * 2;
    // B: row = wn*WTN + p*16 + (grp>>1)*8 + lr ; koff = ks*16 + (grp&1)*8
    uint32_t boff[2][NAT / 2];
    #pragma unroll
    for (int ks = 0; ks < 2; ks++)
        #pragma unroll
        for (int p = 0; p < NAT / 2; p++)
            boff[ks][p] = STG_A + (wn * WTN + p * 16 + (grp >> 1) * 8 + lr) * ROWB +
                          (ks * 16 + (grp & 1) * 8) * 2;

    for (int c = 0; c < nch; c++) {
        CP_WAIT(STAGES - 2);
        __syncthreads();
        int nc = c + STAGES - 1;
        if (nc < nch) {
            int st = nc % STAGES;
            #pragma unroll
            for (int i = 0; i < A_OPS; i++) CP16(dstA[i] + st * STG, srcA[i] + nc * 32);
            #pragma unroll
            for (int i = 0; i < B_OPS; i++) CP16(dstB[i] + st * STG, srcB[i] + nc * 32);
        }
        CP_COMMIT();

        uint32_t base = sb + (c % STAGES) * STG;
        #pragma unroll
        for (int ks = 0; ks < 2; ks++) {
            uint32_t a[2][4];
            uint32_t b[NAT][2];
            #pragma unroll
            for (int ma = 0; ma < 2; ma++)
                LDSM4(a[ma][0], a[ma][1], a[ma][2], a[ma][3], base + aoff[ks][ma]);
            #pragma unroll
            for (int p = 0; p < NAT / 2; p++)
                LDSM4(b[2 * p][0], b[2 * p][1], b[2 * p + 1][0], b[2 * p + 1][1],
                      base + boff[ks][p]);
            #pragma unroll
            for (int ma = 0; ma < 2; ma++)
                #pragma unroll
                for (int na = 0; na < NAT; na++)
                    asm volatile(
                        "mma.sync.aligned.m16n8k16.row.col.f32.bf16.bf16.f32 "
                        "{%0,%1,%2,%3}, {%4,%5,%6,%7}, {%8,%9}, {%0,%1,%2,%3};"
                        : "+f"(acc[ma][na][0]), "+f"(acc[ma][na][1]),
                          "+f"(acc[ma][na][2]), "+f"(acc[ma][na][3])
                        : "r"(a[ma][0]), "r"(a[ma][1]), "r"(a[ma][2]), "r"(a[ma][3]),
                          "r"(b[na][0]), "r"(b[na][1]));
        }
    }

    // epilogue
    int tr = lane >> 2, tc = (lane & 3) * 2;
    #pragma unroll
    for (int ma = 0; ma < 2; ma++) {
        int row = bm + wm * 32 + ma * 16 + tr;
        #pragma unroll
        for (int na = 0; na < NAT; na++) {
            int col = bn + wn * WTN + na * 8 + tc;
            float2 bv = *(const float2*)(bias + col);
            float v0 = acc[ma][na][0] + bv.x;
            float v1 = acc[ma][na][1] + bv.y;
            float v2 = acc[ma][na][2] + bv.x;
            float v3 = acc[ma][na][3] + bv.y;
            if (MODE == 1) {
                v0 = gelu_tanh(v0); v1 = gelu_tanh(v1);
                v2 = gelu_tanh(v2); v3 = gelu_tanh(v3);
            }
            if (MODE == 2) {
                float2 gv = *(const float2*)(gate + col);
                float2 x0 = *(const float2*)(X + (size_t)row * N + col);
                float2 x1 = *(const float2*)(X + (size_t)(row + 8) * N + col);
                v0 = x0.x + v0 * gv.x; v1 = x0.y + v1 * gv.y;
                v2 = x1.x + v2 * gv.x; v3 = x1.y + v3 * gv.y;
            }
            *(float2*)(C + (size_t)row * N + col)       = make_float2(v0, v1);
            *(float2*)(C + (size_t)(row + 8) * N + col) = make_float2(v2, v3);
        }
    }
}

// ---------------- mod/gate precompute ----------------
__global__ void modgate_kernel(const float* __restrict__ cond,
                               const float* __restrict__ a1w, const float* __restrict__ a1b,
                               const float* __restrict__ g1w, const float* __restrict__ g1b,
                               const float* __restrict__ a2w, const float* __restrict__ a2b,
                               const float* __restrict__ g2w, const float* __restrict__ g2b,
                               float* __restrict__ out) {
    __shared__ float cs[D_MODEL];
    for (int i = threadIdx.x; i < D_MODEL; i += blockDim.x) cs[i] = cond[i];
    __syncthreads();
    int o = blockIdx.x * blockDim.x + threadIdx.x;
    int l = o / (6 * D_MODEL);
    int j = o % (6 * D_MODEL);
    const float* W; const float* Bv; int col, ncols;
    if (j < 2 * D_MODEL)      { W = a1w + (size_t)l * D_MODEL * 2 * D_MODEL; Bv = a1b + l * 2 * D_MODEL; col = j;               ncols = 2 * D_MODEL; }
    else if (j < 3 * D_MODEL) { W = g1w + (size_t)l * D_MODEL * D_MODEL;     Bv = g1b + l * D_MODEL;     col = j - 2 * D_MODEL; ncols = D_MODEL; }
    else if (j < 5 * D_MODEL) { W = a2w + (size_t)l * D_MODEL * 2 * D_MODEL; Bv = a2b + l * 2 * D_MODEL; col = j - 3 * D_MODEL; ncols = 2 * D_MODEL; }
    else                      { W = g2w + (size_t)l * D_MODEL * D_MODEL;     Bv = g2b + l * D_MODEL;     col = j - 5 * D_MODEL; ncols = D_MODEL; }
    float acc = 0.f;
    #pragma unroll 8
    for (int d = 0; d < D_MODEL; d++) acc += cs[d] * W[(size_t)d * ncols + col];
    out[o] = acc + Bv[col];
}

// ---------------- LayerNorm + adaLN modulation ----------------
__global__ void ln_mod_kernel(const float* __restrict__ x,
                              const float* __restrict__ shift,
                              const float* __restrict__ scale,
                              float* __restrict__ h) {
    int row = blockIdx.x;
    int tid = threadIdx.x;
    const float* xr = x + (size_t)row * D_MODEL;
    float v[4], s = 0.f, s2 = 0.f;
    #pragma unroll
    for (int i = 0; i < 4; i++) {
        v[i] = xr[tid + i * 256];
        s += v[i]; s2 += v[i] * v[i];
    }
    #pragma unroll
    for (int off = 16; off; off >>= 1) {
        s  += __shfl_xor_sync(0xffffffff, s,  off);
        s2 += __shfl_xor_sync(0xffffffff, s2, off);
    }
    __shared__ float sh1[8], sh2[8];
    int w = tid >> 5, lane = tid & 31;
    if (lane == 0) { sh1[w] = s; sh2[w] = s2; }
    __syncthreads();
    if (tid == 0) {
        float a = 0.f, b = 0.f;
        #pragma unroll
        for (int i = 0; i < 8; i++) { a += sh1[i]; b += sh2[i]; }
        sh1[0] = a; sh2[0] = b;
    }
    __syncthreads();
    float mean = sh1[0] * (1.f / D_MODEL);
    float var  = sh2[0] * (1.f / D_MODEL) - mean * mean;
    float r = rsqrtf(var + 1e-5f);
    float* hr = h + (size_t)row * D_MODEL;
    #pragma unroll
    for (int i = 0; i < 4; i++) {
        int col = tid + i * 256;
        hr[col] = (v[i] - mean) * r * (1.f + scale[col]) + shift[col];
    }
}

// ---------------- RoPE table (fp64 once) ----------------
__global__ void rope_table_kernel(float* __restrict__ rc, float* __restrict__ rs) {
    int idx = blockIdx.x * 256 + threadIdx.x;  // S*32
    int s = idx >> 5, j = idx & 31;
    double inv = exp(-((double)j / 32.0) * 9.210340371976184);
    double ang = (double)s * inv;
    rc[idx] = (float)cos(ang);
    rs[idx] = (float)sin(ang);
}

// ---------------- per-(token,head) RMSNorm + RoPE ----------------
__global__ void rmsrope_kernel(float* __restrict__ qkv,
                               const float* __restrict__ rc,
                               const float* __restrict__ rs) {
    int s = blockIdx.x;
    int warp = threadIdx.x >> 5, lane = threadIdx.x & 31;
    int hh = blockIdx.y * 8 + warp;          // 0..31
    int which = hh >> 4;
    int h = hh & 15;
    float* base = qkv + (size_t)s * 3 * D_MODEL + which * D_MODEL + h * DH;
    float x1 = base[lane], x2 = base[lane + 32];
    float ss = x1 * x1 + x2 * x2;
    #pragma unroll
    for (int off = 16; off; off >>= 1) ss += __shfl_xor_sync(0xffffffff, ss, off);
    float r = rsqrtf(ss * (1.f / DH) + 1e-6f);
    x1 *= r; x2 *= r;
    float c = rc[s * 32 + lane], sn = rs[s * 32 + lane];
    base[lane]      = x1 * c - x2 * sn;
    base[lane + 32] = x1 * sn + x2 * c;
}

// ---------------- frame-masked flash attention ----------------
__global__ void __launch_bounds__(256, 4)
attn_kernel(const float* __restrict__ qkv, float* __restrict__ O, int window) {
    int f = blockIdx.x;
    int h = blockIdx.y;
    int tid = threadIdx.x;
    int warp = tid >> 5, lane = tid & 31;
    __shared__ float Qs[8][DH];
    __shared__ float Ks[32][DH + 4];
    __shared__ float Vs[32][DH + 2];
    int h0 = h * DH;
    int qrow0 = f * TPF;
    for (int i = tid; i < 8 * DH; i += 256) {
        int r = i >> 6, d = i & 63;
        Qs[r][d] = qkv[(size_t)(qrow0 + r) * 3 * D_MODEL + h0 + d];
    }
    __syncthreads();

    int fstart = max(0, f - window + 1);
    int kstart = fstart * TPF;
    int kend = (f + 1) * TPF;
    int nk = kend - kstart;

    float m = -1e30f, l = 0.f;
    float o0 = 0.f, o1 = 0.f;
    int q = warp;
    int d0 = lane * 2;
    const float sc = 0.125f;

    for (int c0 = 0; c0 < nk; c0 += 32) {
        for (int i = tid; i < 32 * DH; i += 256) {
            int r = i >> 6, d = i & 63;
            int kr = kstart + c0 + r;
            if (kr > S_LEN - 1) kr = S_LEN - 1;
            Ks[r][d] = qkv[(size_t)kr * 3 * D_MODEL + D_MODEL + h0 + d];
            Vs[r][d] = qkv[(size_t)kr * 3 * D_MODEL + 2 * D_MODEL + h0 + d];
        }
        __syncthreads();

        float s;
        if (c0 + lane < nk) {
            float a0 = 0.f, a1 = 0.f, a2 = 0.f, a3 = 0.f;
            #pragma unroll
            for (int d = 0; d < DH; d += 4) {
                a0 = fmaf(Qs[q][d],     Ks[lane][d],     a0);
                a1 = fmaf(Qs[q][d + 1], Ks[lane][d + 1], a1);
                a2 = fmaf(Qs[q][d + 2], Ks[lane][d + 2], a2);
                a3 = fmaf(Qs[q][d + 3], Ks[lane][d + 3], a3);
            }
            s = (a0 + a1 + a2 + a3) * sc;
        } else {
            s = -1e30f;
        }
        float cm = s;
        #pragma unroll
        for (int off = 16; off; off >>= 1) cm = fmaxf(cm, __shfl_xor_sync(0xffffffff, cm, off));
        float mnew = fmaxf(m, cm);
        float p = __expf(s - mnew);
        if (c0 + lane >= nk) p = 0.f;
        float ps = p;
        #pragma unroll
        for (int off = 16; off; off >>= 1) ps += __shfl_xor_sync(0xffffffff, ps, off);
        float factor = __expf(m - mnew);
        l = l * factor + ps;
        m = mnew;
        o0 *= factor; o1 *= factor;
        #pragma unroll
        for (int k = 0; k < 32; k++) {
            float pk = __shfl_sync(0xffffffff, p, k);
            o0 = fmaf(pk, Vs[k][d0],     o0);
            o1 = fmaf(pk, Vs[k][d0 + 1], o1);
        }
        __syncthreads();
    }
    float invl = 1.f / l;
    O[(size_t)(qrow0 + q) * D_MODEL + h0 + d0]     = o0 * invl;
    O[(size_t)(qrow0 + q) * D_MODEL + h0 + d0 + 1] = o1 * invl;
}

// ---------------- host-side orchestration ----------------
extern "C" void kernel_launch(void* const* d_in, const int* in_sizes, int n_in,
                              void* d_out, int out_size) {
    const float* x       = (const float*)d_in[0];
    const float* cond    = (const float*)d_in[1];
    const float* qkv_w   = (const float*)d_in[2];
    const float* qkv_b   = (const float*)d_in[3];
    const float* out_w   = (const float*)d_in[4];
    const float* out_b   = (const float*)d_in[5];
    const float* mlp_w1  = (const float*)d_in[6];
    const float* mlp_b1  = (const float*)d_in[7];
    const float* mlp_w2  = (const float*)d_in[8];
    const float* mlp_b2  = (const float*)d_in[9];
    const float* ada1_w  = (const float*)d_in[10];
    const float* ada1_b  = (const float*)d_in[11];
    const float* gate1_w = (const float*)d_in[12];
    const float* gate1_b = (const float*)d_in[13];
    const float* ada2_w  = (const float*)d_in[14];
    const float* ada2_b  = (const float*)d_in[15];
    const float* gate2_w = (const float*)d_in[16];
    const float* gate2_b = (const float*)d_in[17];
    float* X = (float*)d_out;

    float *h_ptr, *qkv_ptr, *attno_ptr, *ff_ptr, *mod_ptr, *rc_ptr, *rs_ptr;
    __nv_bfloat16 *abuf, *wbuf;
    cudaGetSymbolAddress((void**)&h_ptr,     g_h);
    cudaGetSymbolAddress((void**)&qkv_ptr,   g_qkv);
    cudaGetSymbolAddress((void**)&attno_ptr, g_attno);
    cudaGetSymbolAddress((void**)&ff_ptr,    g_ff);
    cudaGetSymbolAddress((void**)&mod_ptr,   g_mod);
    cudaGetSymbolAddress((void**)&rc_ptr,    g_ropec);
    cudaGetSymbolAddress((void**)&rs_ptr,    g_ropes);
    cudaGetSymbolAddress((void**)&abuf,      g_abuf);
    cudaGetSymbolAddress((void**)&wbuf,      g_wbuf);

    // dynamic SMEM sizes: (BM + 128) * 80 * 3 stages
    const int SMEM_128 = (128 + 128) * 80 * 3;  // 61440
    const int SMEM_64  = (64 + 128) * 80 * 3;   // 46080
    cudaFuncSetAttribute(mma_gemm<0, 128>, cudaFuncAttributeMaxDynamicSharedMemorySize, SMEM_128);
    cudaFuncSetAttribute(mma_gemm<1, 128>, cudaFuncAttributeMaxDynamicSharedMemorySize, SMEM_128);
    cudaFuncSetAttribute(mma_gemm<2, 64>,  cudaFuncAttributeMaxDynamicSharedMemorySize, SMEM_64);

    cudaMemcpyAsync(X, x, (size_t)S_LEN * D_MODEL * sizeof(float), cudaMemcpyDeviceToDevice);

    rope_table_kernel<<<S_LEN * 32 / 256, 256>>>(rc_ptr, rs_ptr);

    modgate_kernel<<<L_LAYERS * 6 * D_MODEL / 256, 256>>>(
        cond, ada1_w, ada1_b, gate1_w, gate1_b, ada2_w, ada2_b, gate2_w, gate2_b, mod_ptr);

    for (int i = 0; i < L_LAYERS; i++) {
        const float* mod = mod_ptr + i * 6 * D_MODEL;
        int window = (i % 4 == 0) ? 128 : 8;

        // ---- attention block ----
        ln_mod_kernel<<<S_LEN, 256>>>(X, mod, mod + D_MODEL, h_ptr);

        split_act_kernel<<<S_LEN * D_MODEL / 256, 256>>>(h_ptr, abuf, 10);
        split_wT_kernel<<<dim3(3 * D_MODEL / 32, D_MODEL / 32), dim3(32, 8)>>>(
            qkv_w + (size_t)i * D_MODEL * 3 * D_MODEL, wbuf, D_MODEL, 3 * D_MODEL);
        mma_gemm<0, 128><<<dim3(3 * D_MODEL / 128, S_LEN / 128), 256, SMEM_128>>>(
            abuf, wbuf, qkv_b + i * 3 * D_MODEL, nullptr, qkv_ptr, nullptr,
            S_LEN, 3 * D_MODEL, 3 * D_MODEL);

        rmsrope_kernel<<<dim3(S_LEN, 4), 256>>>(qkv_ptr, rc_ptr, rs_ptr);
        attn_kernel<<<dim3(NFRAMES, NH), 256>>>(qkv_ptr, attno_ptr, window);

        split_act_kernel<<<S_LEN * D_MODEL / 256, 256>>>(attno_ptr, abuf, 10);
        split_wT_kernel<<<dim3(D_MODEL / 32, D_MODEL / 32), dim3(32, 8)>>>(
            out_w + (size_t)i * D_MODEL * D_MODEL, wbuf, D_MODEL, D_MODEL);
        mma_gemm<2, 64><<<dim3(D_MODEL / 128, S_LEN / 64), 256, SMEM_64>>>(
            abuf, wbuf, out_b + i * D_MODEL, mod + 2 * D_MODEL, X, X,
            S_LEN, D_MODEL, 3 * D_MODEL);

        // ---- MLP block ----
        ln_mod_kernel<<<S_LEN, 256>>>(X, mod + 3 * D_MODEL, mod + 4 * D_MODEL, h_ptr);

        split_act_kernel<<<S_LEN * D_MODEL / 256, 256>>>(h_ptr, abuf, 10);
        split_wT_kernel<<<dim3(DFF / 32, D_MODEL / 32), dim3(32, 8)>>>(
            mlp_w1 + (size_t)i * D_MODEL * DFF, wbuf, D_MODEL, DFF);
        mma_gemm<1, 128><<<dim3(DFF / 128, S_LEN / 128), 256, SMEM_128>>>(
            abuf, wbuf, mlp_b1 + i * DFF, nullptr, ff_ptr, nullptr,
            S_LEN, DFF, 3 * D_MODEL);

        split_act_kernel<<<S_LEN * DFF / 256, 256>>>(ff_ptr, abuf, 12);
        split_wT_kernel<<<dim3(D_MODEL / 32, DFF / 32), dim3(32, 8)>>>(
            mlp_w2 + (size_t)i * DFF * D_MODEL, wbuf, DFF, D_MODEL);
        mma_gemm<2, 64><<<dim3(D_MODEL / 128, S_LEN / 64), 256, SMEM_64>>>(
            abuf, wbuf, mlp_b2 + i * D_MODEL, mod + 5 * D_MODEL, X, X,
            S_LEN, D_MODEL, 3 * DFF);
    }
}

// round 6
// speedup vs baseline: 3.2793x; 1.0708x over previous
#include <cuda_runtime.h>
#include <cuda_bf16.h>
#include <math.h>
#include <stdint.h>

#define S_LEN 1024
#define D_MODEL 1024
#define NH 16
#define DH 64
#define L_LAYERS 4
#define DFF 4096
#define TPF 8
#define NFRAMES (S_LEN / TPF)

// ---------------- scratch (device globals; no allocation) ----------------
__device__ float g_qkv[S_LEN * 3 * D_MODEL];
__device__ float g_mod[L_LAYERS * 6 * D_MODEL];
__device__ float g_ropec[S_LEN * 32];
__device__ float g_ropes[S_LEN * 32];
// act split buffers: [M, 2K] bf16 (hi block | lo block)
__device__ __nv_bfloat16 g_abuf[1024 * 2048];    // K=1024 activations
__device__ __nv_bfloat16 g_abuf2[1024 * 8192];   // K=4096 (mlp hidden)
// weight split buffer: [2K, N] bf16 (hi rows | lo rows)
__device__ __nv_bfloat16 g_wbuf[8192 * 1024];    // max 8M elems

// ---------------- helpers ----------------
__device__ __forceinline__ uint32_t smem_u32(const void* p) {
    uint32_t a;
    asm("{ .reg .u64 t; cvta.to.shared.u64 t, %1; cvt.u32.u64 %0, t; }" : "=r"(a) : "l"(p));
    return a;
}
#define CP16(dst, src) \
    asm volatile("cp.async.cg.shared.global [%0], [%1], 16;" :: "r"(dst), "l"(src))
#define CP_COMMIT() asm volatile("cp.async.commit_group;")
#define CP_WAIT(n)  asm volatile("cp.async.wait_group %0;" :: "n"(n))
#define LDSM4(r0, r1, r2, r3, addr)                                        \
    asm volatile("ldmatrix.sync.aligned.m8n8.x4.shared.b16 {%0,%1,%2,%3}, [%4];" \
        : "=r"(r0), "=r"(r1), "=r"(r2), "=r"(r3) : "r"(addr))
#define LDSM4T(r0, r1, r2, r3, addr)                                       \
    asm volatile("ldmatrix.sync.aligned.m8n8.x4.trans.shared.b16 {%0,%1,%2,%3}, [%4];" \
        : "=r"(r0), "=r"(r1), "=r"(r2), "=r"(r3) : "r"(addr))

__device__ __forceinline__ float gelu_tanh(float v) {
    float t = tanhf(0.7978845608028654f * (v + 0.044715f * v * v * v));
    return 0.5f * v * (1.f + t);
}

// split-write two consecutive values (hi at col, lo at col+N) in a [rows, 2N] buffer
__device__ __forceinline__ void store_split2(__nv_bfloat16* Cs, size_t rowbase, int col,
                                             int N, float a, float b) {
    __nv_bfloat162 hi, lo;
    hi.x = __float2bfloat16(a);
    hi.y = __float2bfloat16(b);
    lo.x = __float2bfloat16(a - __bfloat162float(hi.x));
    lo.y = __float2bfloat16(b - __bfloat162float(hi.y));
    *(__nv_bfloat162*)(Cs + rowbase + col)     = hi;
    *(__nv_bfloat162*)(Cs + rowbase + N + col) = lo;
}

// ---------------- weight split (no transpose): W [K,N] fp32 -> [2K,N] bf16 ----------------
__global__ void split_w_kernel(const float* __restrict__ W, __nv_bfloat16* __restrict__ out,
                               int K, int N) {
    int n0 = blockIdx.x * 1024 + threadIdx.x * 4;
    int k = blockIdx.y;
    float4 w = *(const float4*)(W + (size_t)k * N + n0);
    __nv_bfloat162 h0, h1, l0, l1;
    h0.x = __float2bfloat16(w.x); h0.y = __float2bfloat16(w.y);
    h1.x = __float2bfloat16(w.z); h1.y = __float2bfloat16(w.w);
    l0.x = __float2bfloat16(w.x - __bfloat162float(h0.x));
    l0.y = __float2bfloat16(w.y - __bfloat162float(h0.y));
    l1.x = __float2bfloat16(w.z - __bfloat162float(h1.x));
    l1.y = __float2bfloat16(w.w - __bfloat162float(h1.y));
    uint2 hu, lu;
    hu.x = *(uint32_t*)&h0; hu.y = *(uint32_t*)&h1;
    lu.x = *(uint32_t*)&l0; lu.y = *(uint32_t*)&l1;
    *(uint2*)(out + (size_t)k * N + n0)       = hu;
    *(uint2*)(out + (size_t)(K + k) * N + n0) = lu;
}

// ---------------- mma.sync bf16 GEMM ----------------
// logical C[M,N] = A'[M,3K] . B'[3K,N], A'=[hi|lo|hi], B'=[hi;hi;lo] along K.
// physical A [M,2K] (hi|lo), B [2K,N] (hi rows; lo rows); chunk remap inside.
// MODE 0: C = acc + bias (fp32)
// MODE 1: Cs = bf16split(gelu(acc + bias))   (Cs is [M, 2N])
// MODE 2: C = X + (acc + bias) * gate (fp32)
template <int MODE, int BM>
__global__ void __launch_bounds__(256, 2)
mma_gemm(const __nv_bfloat16* __restrict__ A, const __nv_bfloat16* __restrict__ B,
         const float* __restrict__ bias, const float* __restrict__ gate,
         float* __restrict__ C, __nv_bfloat16* __restrict__ Cs,
         const float* __restrict__ X, int M, int N, int K) {
    constexpr int WARPS_M = BM / 32;
    constexpr int WARPS_N = 8 / WARPS_M;
    constexpr int WTN = 128 / WARPS_N;   // 64 or 32
    constexpr int NAT = WTN / 8;         // 8 or 4
    constexpr int STAGES = 3;
    constexpr int ROWA = 80;             // A smem row stride (32 bf16 + pad)
    constexpr int ROWB = 272;            // B smem row stride (128 bf16 + pad)
    constexpr int STG_A = BM * ROWA;
    constexpr int STG_B = 32 * ROWB;
    constexpr int STG = STG_A + STG_B;
    constexpr int A_OPS = BM / 64;       // 16B cp ops per thread for A
    constexpr int B_OPS = 2;

    extern __shared__ __align__(128) char dyn[];
    uint32_t sb = smem_u32(dyn);
    int tid = threadIdx.x;
    int wid = tid >> 5, lane = tid & 31;
    int wm = wid / WARPS_N, wn = wid % WARPS_N;
    int bm = blockIdx.y * BM, bn = blockIdx.x * 128;

    float acc[2][NAT][4];
    #pragma unroll
    for (int i = 0; i < 2; i++)
        #pragma unroll
        for (int j = 0; j < NAT; j++)
            #pragma unroll
            for (int q = 0; q < 4; q++) acc[i][j][q] = 0.f;

    int nK32 = K >> 5;
    int nch = 3 * nK32;

    // per-thread cp.async bases
    const __nv_bfloat16* baseA[A_OPS];
    uint32_t dstA[A_OPS];
    #pragma unroll
    for (int i = 0; i < A_OPS; i++) {
        int idx = tid + i * 256;
        int r = idx >> 2, seg = idx & 3;
        baseA[i] = A + (size_t)(bm + r) * (2 * K) + seg * 8;
        dstA[i] = sb + r * ROWA + seg * 16;
    }
    const __nv_bfloat16* baseB[B_OPS];
    uint32_t dstB[B_OPS];
    #pragma unroll
    for (int i = 0; i < B_OPS; i++) {
        int idx = tid + i * 256;
        int r = idx >> 4, seg = idx & 15;
        baseB[i] = B + (size_t)r * N + bn + seg * 8;
        dstB[i] = sb + STG_A + r * ROWB + seg * 16;
    }

    // prologue
    #pragma unroll
    for (int s = 0; s < STAGES - 1; s++) {
        int ka = (s < 2 * nK32) ? s : s - 2 * nK32;
        int kb = (s < nK32) ? s : s - nK32;
        #pragma unroll
        for (int i = 0; i < A_OPS; i++) CP16(dstA[i] + s * STG, baseA[i] + ka * 32);
        #pragma unroll
        for (int i = 0; i < B_OPS; i++) CP16(dstB[i] + s * STG, baseB[i] + (size_t)kb * 32 * N);
        CP_COMMIT();
    }

    // ldmatrix offsets
    int grp = lane >> 3, lr = lane & 7;
    uint32_t aoff[2][2];
    #pragma unroll
    for (int ks = 0; ks < 2; ks++)
        #pragma unroll
        for (int ma = 0; ma < 2; ma++)
            aoff[ks][ma] = (wm * 32 + ma * 16 + (grp & 1) * 8 + lr) * ROWA +
                           (ks * 16 + (grp >> 1) * 8) * 2;
    // B trans: lanes 0-7 -> k rows; bit3 of lane -> k+8; bit4 -> n+8
    uint32_t boff[2][NAT / 2];
    #pragma unroll
    for (int ks = 0; ks < 2; ks++)
        #pragma unroll
        for (int p = 0; p < NAT / 2; p++)
            boff[ks][p] = STG_A + (ks * 16 + lr + (grp & 1) * 8) * ROWB +
                          (wn * WTN + p * 16 + ((lane >> 4) & 1) * 8) * 2;

    for (int c = 0; c < nch; c++) {
        CP_WAIT(STAGES - 2);
        __syncthreads();
        int nc = c + STAGES - 1;
        if (nc < nch) {
            int st = nc % STAGES;
            int ka = (nc < 2 * nK32) ? nc : nc - 2 * nK32;
            int kb = (nc < nK32) ? nc : nc - nK32;
            #pragma unroll
            for (int i = 0; i < A_OPS; i++) CP16(dstA[i] + st * STG, baseA[i] + ka * 32);
            #pragma unroll
            for (int i = 0; i < B_OPS; i++) CP16(dstB[i] + st * STG, baseB[i] + (size_t)kb * 32 * N);
        }
        CP_COMMIT();

        uint32_t base = sb + (c % STAGES) * STG;
        #pragma unroll
        for (int ks = 0; ks < 2; ks++) {
            uint32_t a[2][4];
            uint32_t b[NAT][2];
            #pragma unroll
            for (int ma = 0; ma < 2; ma++)
                LDSM4(a[ma][0], a[ma][1], a[ma][2], a[ma][3], base + aoff[ks][ma]);
            #pragma unroll
            for (int p = 0; p < NAT / 2; p++)
                LDSM4T(b[2 * p][0], b[2 * p][1], b[2 * p + 1][0], b[2 * p + 1][1],
                       base + boff[ks][p]);
            #pragma unroll
            for (int ma = 0; ma < 2; ma++)
                #pragma unroll
                for (int na = 0; na < NAT; na++)
                    asm volatile(
                        "mma.sync.aligned.m16n8k16.row.col.f32.bf16.bf16.f32 "
                        "{%0,%1,%2,%3}, {%4,%5,%6,%7}, {%8,%9}, {%0,%1,%2,%3};"
                        : "+f"(acc[ma][na][0]), "+f"(acc[ma][na][1]),
                          "+f"(acc[ma][na][2]), "+f"(acc[ma][na][3])
                        : "r"(a[ma][0]), "r"(a[ma][1]), "r"(a[ma][2]), "r"(a[ma][3]),
                          "r"(b[na][0]), "r"(b[na][1]));
        }
    }

    // epilogue
    int tr = lane >> 2, tc = (lane & 3) * 2;
    #pragma unroll
    for (int ma = 0; ma < 2; ma++) {
        int row = bm + wm * 32 + ma * 16 + tr;
        #pragma unroll
        for (int na = 0; na < NAT; na++) {
            int col = bn + wn * WTN + na * 8 + tc;
            float2 bv = *(const float2*)(bias + col);
            float v0 = acc[ma][na][0] + bv.x;
            float v1 = acc[ma][na][1] + bv.y;
            float v2 = acc[ma][na][2] + bv.x;
            float v3 = acc[ma][na][3] + bv.y;
            if (MODE == 1) {
                v0 = gelu_tanh(v0); v1 = gelu_tanh(v1);
                v2 = gelu_tanh(v2); v3 = gelu_tanh(v3);
                store_split2(Cs, (size_t)row * 2 * N, col, N, v0, v1);
                store_split2(Cs, (size_t)(row + 8) * 2 * N, col, N, v2, v3);
            } else {
                if (MODE == 2) {
                    float2 gv = *(const float2*)(gate + col);
                    float2 x0 = *(const float2*)(X + (size_t)row * N + col);
                    float2 x1 = *(const float2*)(X + (size_t)(row + 8) * N + col);
                    v0 = x0.x + v0 * gv.x; v1 = x0.y + v1 * gv.y;
                    v2 = x1.x + v2 * gv.x; v3 = x1.y + v3 * gv.y;
                }
                *(float2*)(C + (size_t)row * N + col)       = make_float2(v0, v1);
                *(float2*)(C + (size_t)(row + 8) * N + col) = make_float2(v2, v3);
            }
        }
    }
}

// ---------------- mod/gate precompute ----------------
__global__ void modgate_kernel(const float* __restrict__ cond,
                               const float* __restrict__ a1w, const float* __restrict__ a1b,
                               const float* __restrict__ g1w, const float* __restrict__ g1b,
                               const float* __restrict__ a2w, const float* __restrict__ a2b,
                               const float* __restrict__ g2w, const float* __restrict__ g2b,
                               float* __restrict__ out) {
    __shared__ float cs[D_MODEL];
    for (int i = threadIdx.x; i < D_MODEL; i += blockDim.x) cs[i] = cond[i];
    __syncthreads();
    int o = blockIdx.x * blockDim.x + threadIdx.x;
    int l = o / (6 * D_MODEL);
    int j = o % (6 * D_MODEL);
    const float* W; const float* Bv; int col, ncols;
    if (j < 2 * D_MODEL)      { W = a1w + (size_t)l * D_MODEL * 2 * D_MODEL; Bv = a1b + l * 2 * D_MODEL; col = j;               ncols = 2 * D_MODEL; }
    else if (j < 3 * D_MODEL) { W = g1w + (size_t)l * D_MODEL * D_MODEL;     Bv = g1b + l * D_MODEL;     col = j - 2 * D_MODEL; ncols = D_MODEL; }
    else if (j < 5 * D_MODEL) { W = a2w + (size_t)l * D_MODEL * 2 * D_MODEL; Bv = a2b + l * 2 * D_MODEL; col = j - 3 * D_MODEL; ncols = 2 * D_MODEL; }
    else                      { W = g2w + (size_t)l * D_MODEL * D_MODEL;     Bv = g2b + l * D_MODEL;     col = j - 5 * D_MODEL; ncols = D_MODEL; }
    float acc = 0.f;
    #pragma unroll 8
    for (int d = 0; d < D_MODEL; d++) acc += cs[d] * W[(size_t)d * ncols + col];
    out[o] = acc + Bv[col];
}

// ---------------- LayerNorm + adaLN modulation, fused bf16 split out ----------------
__global__ void ln_mod_kernel(const float* __restrict__ x,
                              const float* __restrict__ shift,
                              const float* __restrict__ scale,
                              __nv_bfloat16* __restrict__ out) {  // [S, 2048]
    int row = blockIdx.x;
    int tid = threadIdx.x;
    const float* xr = x + (size_t)row * D_MODEL;
    float v[4], s = 0.f, s2 = 0.f;
    #pragma unroll
    for (int i = 0; i < 4; i++) {
        v[i] = xr[tid + i * 256];
        s += v[i]; s2 += v[i] * v[i];
    }
    #pragma unroll
    for (int off = 16; off; off >>= 1) {
        s  += __shfl_xor_sync(0xffffffff, s,  off);
        s2 += __shfl_xor_sync(0xffffffff, s2, off);
    }
    __shared__ float sh1[8], sh2[8];
    int w = tid >> 5, lane = tid & 31;
    if (lane == 0) { sh1[w] = s; sh2[w] = s2; }
    __syncthreads();
    if (tid == 0) {
        float a = 0.f, b = 0.f;
        #pragma unroll
        for (int i = 0; i < 8; i++) { a += sh1[i]; b += sh2[i]; }
        sh1[0] = a; sh2[0] = b;
    }
    __syncthreads();
    float mean = sh1[0] * (1.f / D_MODEL);
    float var  = sh2[0] * (1.f / D_MODEL) - mean * mean;
    float r = rsqrtf(var + 1e-5f);
    __nv_bfloat16* orow = out + (size_t)row * 2 * D_MODEL;
    #pragma unroll
    for (int i = 0; i < 4; i++) {
        int col = tid + i * 256;
        float hv = (v[i] - mean) * r * (1.f + scale[col]) + shift[col];
        __nv_bfloat16 hi = __float2bfloat16(hv);
        orow[col]           = hi;
        orow[D_MODEL + col] = __float2bfloat16(hv - __bfloat162float(hi));
    }
}

// ---------------- RoPE table (fp64 once) ----------------
__global__ void rope_table_kernel(float* __restrict__ rc, float* __restrict__ rs) {
    int idx = blockIdx.x * 256 + threadIdx.x;  // S*32
    int s = idx >> 5, j = idx & 31;
    double inv = exp(-((double)j / 32.0) * 9.210340371976184);
    double ang = (double)s * inv;
    rc[idx] = (float)cos(ang);
    rs[idx] = (float)sin(ang);
}

// ---------------- per-(token,head) RMSNorm + RoPE ----------------
__global__ void rmsrope_kernel(float* __restrict__ qkv,
                               const float* __restrict__ rc,
                               const float* __restrict__ rs) {
    int s = blockIdx.x;
    int warp = threadIdx.x >> 5, lane = threadIdx.x & 31;
    int hh = blockIdx.y * 8 + warp;
    int which = hh >> 4;
    int h = hh & 15;
    float* base = qkv + (size_t)s * 3 * D_MODEL + which * D_MODEL + h * DH;
    float x1 = base[lane], x2 = base[lane + 32];
    float ss = x1 * x1 + x2 * x2;
    #pragma unroll
    for (int off = 16; off; off >>= 1) ss += __shfl_xor_sync(0xffffffff, ss, off);
    float r = rsqrtf(ss * (1.f / DH) + 1e-6f);
    x1 *= r; x2 *= r;
    float c = rc[s * 32 + lane], sn = rs[s * 32 + lane];
    base[lane]      = x1 * c - x2 * sn;
    base[lane + 32] = x1 * sn + x2 * c;
}

// ---------------- frame-masked flash attention, fused bf16 split output ----------------
__global__ void __launch_bounds__(256, 4)
attn_kernel(const float* __restrict__ qkv, __nv_bfloat16* __restrict__ Oa, int window) {
    int f = blockIdx.x;
    int h = blockIdx.y;
    int tid = threadIdx.x;
    int warp = tid >> 5, lane = tid & 31;
    __shared__ float Qs[8][DH];
    __shared__ float Ks[32][DH + 4];
    __shared__ float Vs[32][DH + 2];
    int h0 = h * DH;
    int qrow0 = f * TPF;
    for (int i = tid; i < 8 * DH; i += 256) {
        int r = i >> 6, d = i & 63;
        Qs[r][d] = qkv[(size_t)(qrow0 + r) * 3 * D_MODEL + h0 + d];
    }
    __syncthreads();

    int fstart = max(0, f - window + 1);
    int kstart = fstart * TPF;
    int kend = (f + 1) * TPF;
    int nk = kend - kstart;

    float m = -1e30f, l = 0.f;
    float o0 = 0.f, o1 = 0.f;
    int q = warp;
    int d0 = lane * 2;
    const float sc = 0.125f;

    for (int c0 = 0; c0 < nk; c0 += 32) {
        for (int i = tid; i < 32 * DH; i += 256) {
            int r = i >> 6, d = i & 63;
            int kr = kstart + c0 + r;
            if (kr > S_LEN - 1) kr = S_LEN - 1;
            Ks[r][d] = qkv[(size_t)kr * 3 * D_MODEL + D_MODEL + h0 + d];
            Vs[r][d] = qkv[(size_t)kr * 3 * D_MODEL + 2 * D_MODEL + h0 + d];
        }
        __syncthreads();

        float s;
        if (c0 + lane < nk) {
            float a0 = 0.f, a1 = 0.f, a2 = 0.f, a3 = 0.f;
            #pragma unroll
            for (int d = 0; d < DH; d += 4) {
                a0 = fmaf(Qs[q][d],     Ks[lane][d],     a0);
                a1 = fmaf(Qs[q][d + 1], Ks[lane][d + 1], a1);
                a2 = fmaf(Qs[q][d + 2], Ks[lane][d + 2], a2);
                a3 = fmaf(Qs[q][d + 3], Ks[lane][d + 3], a3);
            }
            s = (a0 + a1 + a2 + a3) * sc;
        } else {
            s = -1e30f;
        }
        float cm = s;
        #pragma unroll
        for (int off = 16; off; off >>= 1) cm = fmaxf(cm, __shfl_xor_sync(0xffffffff, cm, off));
        float mnew = fmaxf(m, cm);
        float p = __expf(s - mnew);
        if (c0 + lane >= nk) p = 0.f;
        float ps = p;
        #pragma unroll
        for (int off = 16; off; off >>= 1) ps += __shfl_xor_sync(0xffffffff, ps, off);
        float factor = __expf(m - mnew);
        l = l * factor + ps;
        m = mnew;
        o0 *= factor; o1 *= factor;
        #pragma unroll
        for (int k = 0; k < 32; k++) {
            float pk = __shfl_sync(0xffffffff, p, k);
            o0 = fmaf(pk, Vs[k][d0],     o0);
            o1 = fmaf(pk, Vs[k][d0 + 1], o1);
        }
        __syncthreads();
    }
    float invl = 1.f / l;
    float a = o0 * invl, b = o1 * invl;
    __nv_bfloat162 hi, lo;
    hi.x = __float2bfloat16(a);
    hi.y = __float2bfloat16(b);
    lo.x = __float2bfloat16(a - __bfloat162float(hi.x));
    lo.y = __float2bfloat16(b - __bfloat162float(hi.y));
    size_t rb = (size_t)(qrow0 + q) * 2 * D_MODEL;
    *(__nv_bfloat162*)(Oa + rb + h0 + d0)           = hi;
    *(__nv_bfloat162*)(Oa + rb + D_MODEL + h0 + d0) = lo;
}

// ---------------- host-side orchestration ----------------
extern "C" void kernel_launch(void* const* d_in, const int* in_sizes, int n_in,
                              void* d_out, int out_size) {
    const float* x       = (const float*)d_in[0];
    const float* cond    = (const float*)d_in[1];
    const float* qkv_w   = (const float*)d_in[2];
    const float* qkv_b   = (const float*)d_in[3];
    const float* out_w   = (const float*)d_in[4];
    const float* out_b   = (const float*)d_in[5];
    const float* mlp_w1  = (const float*)d_in[6];
    const float* mlp_b1  = (const float*)d_in[7];
    const float* mlp_w2  = (const float*)d_in[8];
    const float* mlp_b2  = (const float*)d_in[9];
    const float* ada1_w  = (const float*)d_in[10];
    const float* ada1_b  = (const float*)d_in[11];
    const float* gate1_w = (const float*)d_in[12];
    const float* gate1_b = (const float*)d_in[13];
    const float* ada2_w  = (const float*)d_in[14];
    const float* ada2_b  = (const float*)d_in[15];
    const float* gate2_w = (const float*)d_in[16];
    const float* gate2_b = (const float*)d_in[17];
    float* X = (float*)d_out;

    float *qkv_ptr, *mod_ptr, *rc_ptr, *rs_ptr;
    __nv_bfloat16 *abuf, *abuf2, *wbuf;
    cudaGetSymbolAddress((void**)&qkv_ptr, g_qkv);
    cudaGetSymbolAddress((void**)&mod_ptr, g_mod);
    cudaGetSymbolAddress((void**)&rc_ptr,  g_ropec);
    cudaGetSymbolAddress((void**)&rs_ptr,  g_ropes);
    cudaGetSymbolAddress((void**)&abuf,    g_abuf);
    cudaGetSymbolAddress((void**)&abuf2,   g_abuf2);
    cudaGetSymbolAddress((void**)&wbuf,    g_wbuf);

    // dynamic SMEM: (BM*80 + 32*272) * 3
    const int SM128 = (128 * 80 + 32 * 272) * 3;  // 56832
    const int SM64  = (64 * 80 + 32 * 272) * 3;   // 41472
    cudaFuncSetAttribute(mma_gemm<0, 128>, cudaFuncAttributeMaxDynamicSharedMemorySize, SM128);
    cudaFuncSetAttribute(mma_gemm<1, 128>, cudaFuncAttributeMaxDynamicSharedMemorySize, SM128);
    cudaFuncSetAttribute(mma_gemm<2, 64>,  cudaFuncAttributeMaxDynamicSharedMemorySize, SM64);

    cudaMemcpyAsync(X, x, (size_t)S_LEN * D_MODEL * sizeof(float), cudaMemcpyDeviceToDevice);

    rope_table_kernel<<<S_LEN * 32 / 256, 256>>>(rc_ptr, rs_ptr);

    modgate_kernel<<<L_LAYERS * 6 * D_MODEL / 256, 256>>>(
        cond, ada1_w, ada1_b, gate1_w, gate1_b, ada2_w, ada2_b, gate2_w, gate2_b, mod_ptr);

    for (int i = 0; i < L_LAYERS; i++) {
        const float* mod = mod_ptr + i * 6 * D_MODEL;
        int window = (i % 4 == 0) ? 128 : 8;

        // ---- attention block ----
        ln_mod_kernel<<<S_LEN, 256>>>(X, mod, mod + D_MODEL, abuf);

        split_w_kernel<<<dim3(3 * D_MODEL / 1024, D_MODEL), 256>>>(
            qkv_w + (size_t)i * D_MODEL * 3 * D_MODEL, wbuf, D_MODEL, 3 * D_MODEL);
        mma_gemm<0, 128><<<dim3(3 * D_MODEL / 128, S_LEN / 128), 256, SM128>>>(
            abuf, wbuf, qkv_b + i * 3 * D_MODEL, nullptr, qkv_ptr, nullptr, nullptr,
            S_LEN, 3 * D_MODEL, D_MODEL);

        rmsrope_kernel<<<dim3(S_LEN, 4), 256>>>(qkv_ptr, rc_ptr, rs_ptr);
        attn_kernel<<<dim3(NFRAMES, NH), 256>>>(qkv_ptr, abuf, window);

        split_w_kernel<<<dim3(D_MODEL / 1024, D_MODEL), 256>>>(
            out_w + (size_t)i * D_MODEL * D_MODEL, wbuf, D_MODEL, D_MODEL);
        mma_gemm<2, 64><<<dim3(D_MODEL / 128, S_LEN / 64), 256, SM64>>>(
            abuf, wbuf, out_b + i * D_MODEL, mod + 2 * D_MODEL, X, nullptr, X,
            S_LEN, D_MODEL, D_MODEL);

        // ---- MLP block ----
        ln_mod_kernel<<<S_LEN, 256>>>(X, mod + 3 * D_MODEL, mod + 4 * D_MODEL, abuf);

        split_w_kernel<<<dim3(DFF / 1024, D_MODEL), 256>>>(
            mlp_w1 + (size_t)i * D_MODEL * DFF, wbuf, D_MODEL, DFF);
        mma_gemm<1, 128><<<dim3(DFF / 128, S_LEN / 128), 256, SM128>>>(
            abuf, wbuf, mlp_b1 + i * DFF, nullptr, nullptr, abuf2, nullptr,
            S_LEN, DFF, D_MODEL);

        split_w_kernel<<<dim3(D_MODEL / 1024, DFF), 256>>>(
            mlp_w2 + (size_t)i * DFF * D_MODEL, wbuf, DFF, D_MODEL);
        mma_gemm<2, 64><<<dim3(D_MODEL / 128, S_LEN / 64), 256, SM64>>>(
            abuf2, wbuf, mlp_b2 + i * D_MODEL, mod + 5 * D_MODEL, X, nullptr, X,
            S_LEN, D_MODEL, DFF);
    }
}

// round 7
// speedup vs baseline: 3.5996x; 1.0977x over previous
#include <cuda_runtime.h>
#include <cuda_bf16.h>
#include <math.h>
#include <stdint.h>

#define S_LEN 1024
#define D_MODEL 1024
#define NH 16
#define DH 64
#define L_LAYERS 4
#define DFF 4096
#define TPF 8
#define NFRAMES (S_LEN / TPF)

// ---------------- scratch (device globals; no allocation) ----------------
__device__ float g_qkv[S_LEN * 3 * D_MODEL];
__device__ float g_mod[L_LAYERS * 6 * D_MODEL];
__device__ float g_ropec[S_LEN * 32];
__device__ float g_ropes[S_LEN * 32];
// act split buffers: [M, 2K] bf16 (hi block | lo block)
__device__ __nv_bfloat16 g_abuf[1024 * 2048];    // K=1024 activations
__device__ __nv_bfloat16 g_abuf2[1024 * 8192];   // K=4096 (mlp hidden)
// weight split buffer: [2K, N] bf16 (hi rows | lo rows)
__device__ __nv_bfloat16 g_wbuf[8192 * 1024];

// ---------------- helpers ----------------
__device__ __forceinline__ uint32_t smem_u32(const void* p) {
    uint32_t a;
    asm("{ .reg .u64 t; cvta.to.shared.u64 t, %1; cvt.u32.u64 %0, t; }" : "=r"(a) : "l"(p));
    return a;
}
#define CP16(dst, src) \
    asm volatile("cp.async.cg.shared.global [%0], [%1], 16;" :: "r"(dst), "l"(src))
#define CP_COMMIT() asm volatile("cp.async.commit_group;")
#define CP_WAIT(n)  asm volatile("cp.async.wait_group %0;" :: "n"(n))
#define LDSM4(r0, r1, r2, r3, addr)                                        \
    asm volatile("ldmatrix.sync.aligned.m8n8.x4.shared.b16 {%0,%1,%2,%3}, [%4];" \
        : "=r"(r0), "=r"(r1), "=r"(r2), "=r"(r3) : "r"(addr))
#define LDSM4T(r0, r1, r2, r3, addr)                                       \
    asm volatile("ldmatrix.sync.aligned.m8n8.x4.trans.shared.b16 {%0,%1,%2,%3}, [%4];" \
        : "=r"(r0), "=r"(r1), "=r"(r2), "=r"(r3) : "r"(addr))
#define MMA(acc, ar, br)                                                   \
    asm volatile(                                                          \
        "mma.sync.aligned.m16n8k16.row.col.f32.bf16.bf16.f32 "             \
        "{%0,%1,%2,%3}, {%4,%5,%6,%7}, {%8,%9}, {%0,%1,%2,%3};"            \
        : "+f"((acc)[0]), "+f"((acc)[1]), "+f"((acc)[2]), "+f"((acc)[3])   \
        : "r"((ar)[0]), "r"((ar)[1]), "r"((ar)[2]), "r"((ar)[3]),          \
          "r"((br)[0]), "r"((br)[1]))

__device__ __forceinline__ float gelu_tanh(float v) {
    float t = tanhf(0.7978845608028654f * (v + 0.044715f * v * v * v));
    return 0.5f * v * (1.f + t);
}

// split-write two consecutive values (hi at col, lo at col+N) in a [rows, 2N] buffer
__device__ __forceinline__ void store_split2(__nv_bfloat16* Cs, size_t rowbase, int col,
                                             int N, float a, float b) {
    __nv_bfloat162 hi, lo;
    hi.x = __float2bfloat16(a);
    hi.y = __float2bfloat16(b);
    lo.x = __float2bfloat16(a - __bfloat162float(hi.x));
    lo.y = __float2bfloat16(b - __bfloat162float(hi.y));
    *(__nv_bfloat162*)(Cs + rowbase + col)     = hi;
    *(__nv_bfloat162*)(Cs + rowbase + N + col) = lo;
}

// ---------------- weight split: W [K,N] fp32 -> [2K,N] bf16 (hi rows | lo rows) ----------------
__global__ void split_w_kernel(const float* __restrict__ W, __nv_bfloat16* __restrict__ out,
                               int K, int N) {
    int n0 = blockIdx.x * 1024 + threadIdx.x * 4;
    int k = blockIdx.y;
    float4 w = *(const float4*)(W + (size_t)k * N + n0);
    __nv_bfloat162 h0, h1, l0, l1;
    h0.x = __float2bfloat16(w.x); h0.y = __float2bfloat16(w.y);
    h1.x = __float2bfloat16(w.z); h1.y = __float2bfloat16(w.w);
    l0.x = __float2bfloat16(w.x - __bfloat162float(h0.x));
    l0.y = __float2bfloat16(w.y - __bfloat162float(h0.y));
    l1.x = __float2bfloat16(w.z - __bfloat162float(h1.x));
    l1.y = __float2bfloat16(w.w - __bfloat162float(h1.y));
    uint2 hu, lu;
    hu.x = *(uint32_t*)&h0; hu.y = *(uint32_t*)&h1;
    lu.x = *(uint32_t*)&l0; lu.y = *(uint32_t*)&l1;
    *(uint2*)(out + (size_t)k * N + n0)       = hu;
    *(uint2*)(out + (size_t)(K + k) * N + n0) = lu;
}

// ---------------- mma.sync bf16 3-term GEMM, single K-pass ----------------
// C = (A_hi+A_lo)(B_hi) + A_hi B_lo  computed as 3 mma groups per K-chunk.
// A [M,2K] bf16 (hi|lo cols), B [2K,N] bf16 (hi rows; lo rows).
// MODE 0: C = acc + bias (fp32)
// MODE 1: Cs = bf16split(gelu(acc + bias))   (Cs is [M, 2N])
// MODE 2: C = X + (acc + bias) * gate (fp32)
template <int MODE, int BM>
__global__ void __launch_bounds__(256, 2)
mma_gemm(const __nv_bfloat16* __restrict__ A, const __nv_bfloat16* __restrict__ B,
         const float* __restrict__ bias, const float* __restrict__ gate,
         float* __restrict__ C, __nv_bfloat16* __restrict__ Cs,
         const float* __restrict__ X, int M, int N, int K) {
    constexpr int WARPS_M = BM / 32;
    constexpr int WARPS_N = 8 / WARPS_M;
    constexpr int WTN = 128 / WARPS_N;   // 64 (BM=128) or 32 (BM=64)
    constexpr int NAT = WTN / 8;         // 8 or 4
    constexpr int ROWA = 80;
    constexpr int ROWB = 272;
    constexpr int OFF_AL = BM * ROWA;        // A_lo slab
    constexpr int OFF_BH = 2 * BM * ROWA;    // B_hi slab
    constexpr int OFF_BL = OFF_BH + 32 * ROWB;
    constexpr int STG = 2 * BM * ROWA + 2 * 32 * ROWB;
    constexpr int A_OPS = BM / 64;       // 16B ops per thread per A slab
    constexpr int B_OPS = 2;             // per B slab

    extern __shared__ __align__(128) char dyn[];
    uint32_t sb = smem_u32(dyn);
    int tid = threadIdx.x;
    int wid = tid >> 5, lane = tid & 31;
    int wm = wid / WARPS_N, wn = wid % WARPS_N;
    int bm = blockIdx.y * BM, bn = blockIdx.x * 128;

    float acc[2][NAT][4];
    #pragma unroll
    for (int i = 0; i < 2; i++)
        #pragma unroll
        for (int j = 0; j < NAT; j++)
            #pragma unroll
            for (int q = 0; q < 4; q++) acc[i][j][q] = 0.f;

    int nch = K >> 5;

    // cp.async thread mapping
    const __nv_bfloat16* srcA[A_OPS];   // hi; lo = +K
    uint32_t dA[A_OPS];
    #pragma unroll
    for (int i = 0; i < A_OPS; i++) {
        int idx = tid + i * 256;
        int r = idx >> 2, seg = idx & 3;
        srcA[i] = A + (size_t)(bm + r) * (2 * K) + seg * 8;
        dA[i] = sb + r * ROWA + seg * 16;
    }
    const __nv_bfloat16* srcB[B_OPS];   // hi; lo = +K*N
    uint32_t dB[B_OPS];
    #pragma unroll
    for (int i = 0; i < B_OPS; i++) {
        int idx = tid + i * 256;
        int r = idx >> 4, seg = idx & 15;
        srcB[i] = B + (size_t)r * N + bn + seg * 8;
        dB[i] = sb + OFF_BH + r * ROWB + seg * 16;
    }

    // issue loads for chunk kc into stage st
    auto issue = [&](int kc, int st) {
        uint32_t so = st * STG;
        #pragma unroll
        for (int i = 0; i < A_OPS; i++) {
            CP16(dA[i] + so, srcA[i] + kc * 32);
            CP16(dA[i] + so + OFF_AL, srcA[i] + K + kc * 32);
        }
        #pragma unroll
        for (int i = 0; i < B_OPS; i++) {
            CP16(dB[i] + so, srcB[i] + (size_t)kc * 32 * N);
            CP16(dB[i] + so + 32 * ROWB, srcB[i] + (size_t)(K + kc * 32) * N);
        }
    };

    // prologue: chunks 0,1 into stages 0,1
    issue(0, 0); CP_COMMIT();
    issue(1, 1); CP_COMMIT();

    // ldsm offsets
    int grp = lane >> 3, lr = lane & 7;
    uint32_t aoff[2][2];
    #pragma unroll
    for (int ks = 0; ks < 2; ks++)
        #pragma unroll
        for (int ma = 0; ma < 2; ma++)
            aoff[ks][ma] = (wm * 32 + ma * 16 + (grp & 1) * 8 + lr) * ROWA +
                           (ks * 16 + (grp >> 1) * 8) * 2;
    uint32_t boff[2][NAT / 2];
    #pragma unroll
    for (int ks = 0; ks < 2; ks++)
        #pragma unroll
        for (int p = 0; p < NAT / 2; p++)
            boff[ks][p] = OFF_BH + (ks * 16 + lr + (grp & 1) * 8) * ROWB +
                          (wn * WTN + p * 16 + ((lane >> 4) & 1) * 8) * 2;

    for (int c = 0; c < nch; c++) {
        CP_WAIT(1);
        __syncthreads();
        uint32_t base = sb + (c & 1) * STG;

        #pragma unroll
        for (int ks = 0; ks < 2; ks++) {
            uint32_t ah[2][4], al[2][4];
            #pragma unroll
            for (int ma = 0; ma < 2; ma++) {
                LDSM4(ah[ma][0], ah[ma][1], ah[ma][2], ah[ma][3], base + aoff[ks][ma]);
                LDSM4(al[ma][0], al[ma][1], al[ma][2], al[ma][3],
                      base + aoff[ks][ma] + OFF_AL);
            }
            // B_hi: aH*bH + aL*bH
            #pragma unroll
            for (int p = 0; p < NAT / 2; p++) {
                uint32_t b0[2], b1[2];
                LDSM4T(b0[0], b0[1], b1[0], b1[1], base + boff[ks][p]);
                #pragma unroll
                for (int ma = 0; ma < 2; ma++) {
                    MMA(acc[ma][2 * p],     ah[ma], b0);
                    MMA(acc[ma][2 * p + 1], ah[ma], b1);
                    MMA(acc[ma][2 * p],     al[ma], b0);
                    MMA(acc[ma][2 * p + 1], al[ma], b1);
                }
            }
            // B_lo: aH*bL
            #pragma unroll
            for (int p = 0; p < NAT / 2; p++) {
                uint32_t b0[2], b1[2];
                LDSM4T(b0[0], b0[1], b1[0], b1[1],
                       base + boff[ks][p] + 32 * ROWB);
                #pragma unroll
                for (int ma = 0; ma < 2; ma++) {
                    MMA(acc[ma][2 * p],     ah[ma], b0);
                    MMA(acc[ma][2 * p + 1], ah[ma], b1);
                }
            }
        }
        __syncthreads();
        if (c + 2 < nch) issue(c + 2, c & 1);
        CP_COMMIT();
    }

    // epilogue
    int tr = lane >> 2, tc = (lane & 3) * 2;
    #pragma unroll
    for (int ma = 0; ma < 2; ma++) {
        int row = bm + wm * 32 + ma * 16 + tr;
        #pragma unroll
        for (int na = 0; na < NAT; na++) {
            int col = bn + wn * WTN + na * 8 + tc;
            float2 bv = *(const float2*)(bias + col);
            float v0 = acc[ma][na][0] + bv.x;
            float v1 = acc[ma][na][1] + bv.y;
            float v2 = acc[ma][na][2] + bv.x;
            float v3 = acc[ma][na][3] + bv.y;
            if (MODE == 1) {
                v0 = gelu_tanh(v0); v1 = gelu_tanh(v1);
                v2 = gelu_tanh(v2); v3 = gelu_tanh(v3);
                store_split2(Cs, (size_t)row * 2 * N, col, N, v0, v1);
                store_split2(Cs, (size_t)(row + 8) * 2 * N, col, N, v2, v3);
            } else {
                if (MODE == 2) {
                    float2 gv = *(const float2*)(gate + col);
                    float2 x0 = *(const float2*)(X + (size_t)row * N + col);
                    float2 x1 = *(const float2*)(X + (size_t)(row + 8) * N + col);
                    v0 = x0.x + v0 * gv.x; v1 = x0.y + v1 * gv.y;
                    v2 = x1.x + v2 * gv.x; v3 = x1.y + v3 * gv.y;
                }
                *(float2*)(C + (size_t)row * N + col)       = make_float2(v0, v1);
                *(float2*)(C + (size_t)(row + 8) * N + col) = make_float2(v2, v3);
            }
        }
    }
}

// ---------------- mod/gate precompute ----------------
__global__ void modgate_kernel(const float* __restrict__ cond,
                               const float* __restrict__ a1w, const float* __restrict__ a1b,
                               const float* __restrict__ g1w, const float* __restrict__ g1b,
                               const float* __restrict__ a2w, const float* __restrict__ a2b,
                               const float* __restrict__ g2w, const float* __restrict__ g2b,
                               float* __restrict__ out) {
    __shared__ float cs[D_MODEL];
    for (int i = threadIdx.x; i < D_MODEL; i += blockDim.x) cs[i] = cond[i];
    __syncthreads();
    int o = blockIdx.x * blockDim.x + threadIdx.x;
    int l = o / (6 * D_MODEL);
    int j = o % (6 * D_MODEL);
    const float* W; const float* Bv; int col, ncols;
    if (j < 2 * D_MODEL)      { W = a1w + (size_t)l * D_MODEL * 2 * D_MODEL; Bv = a1b + l * 2 * D_MODEL; col = j;               ncols = 2 * D_MODEL; }
    else if (j < 3 * D_MODEL) { W = g1w + (size_t)l * D_MODEL * D_MODEL;     Bv = g1b + l * D_MODEL;     col = j - 2 * D_MODEL; ncols = D_MODEL; }
    else if (j < 5 * D_MODEL) { W = a2w + (size_t)l * D_MODEL * 2 * D_MODEL; Bv = a2b + l * 2 * D_MODEL; col = j - 3 * D_MODEL; ncols = 2 * D_MODEL; }
    else                      { W = g2w + (size_t)l * D_MODEL * D_MODEL;     Bv = g2b + l * D_MODEL;     col = j - 5 * D_MODEL; ncols = D_MODEL; }
    float acc = 0.f;
    #pragma unroll 8
    for (int d = 0; d < D_MODEL; d++) acc += cs[d] * W[(size_t)d * ncols + col];
    out[o] = acc + Bv[col];
}

// ---------------- LayerNorm + adaLN modulation, fused bf16 split out ----------------
__global__ void ln_mod_kernel(const float* __restrict__ x,
                              const float* __restrict__ shift,
                              const float* __restrict__ scale,
                              __nv_bfloat16* __restrict__ out) {  // [S, 2048]
    int row = blockIdx.x;
    int tid = threadIdx.x;
    const float* xr = x + (size_t)row * D_MODEL;
    float v[4], s = 0.f, s2 = 0.f;
    #pragma unroll
    for (int i = 0; i < 4; i++) {
        v[i] = xr[tid + i * 256];
        s += v[i]; s2 += v[i] * v[i];
    }
    #pragma unroll
    for (int off = 16; off; off >>= 1) {
        s  += __shfl_xor_sync(0xffffffff, s,  off);
        s2 += __shfl_xor_sync(0xffffffff, s2, off);
    }
    __shared__ float sh1[8], sh2[8];
    int w = tid >> 5, lane = tid & 31;
    if (lane == 0) { sh1[w] = s; sh2[w] = s2; }
    __syncthreads();
    if (tid == 0) {
        float a = 0.f, b = 0.f;
        #pragma unroll
        for (int i = 0; i < 8; i++) { a += sh1[i]; b += sh2[i]; }
        sh1[0] = a; sh2[0] = b;
    }
    __syncthreads();
    float mean = sh1[0] * (1.f / D_MODEL);
    float var  = sh2[0] * (1.f / D_MODEL) - mean * mean;
    float r = rsqrtf(var + 1e-5f);
    __nv_bfloat16* orow = out + (size_t)row * 2 * D_MODEL;
    #pragma unroll
    for (int i = 0; i < 4; i++) {
        int col = tid + i * 256;
        float hv = (v[i] - mean) * r * (1.f + scale[col]) + shift[col];
        __nv_bfloat16 hi = __float2bfloat16(hv);
        orow[col]           = hi;
        orow[D_MODEL + col] = __float2bfloat16(hv - __bfloat162float(hi));
    }
}

// ---------------- RoPE table (fp64 once) ----------------
__global__ void rope_table_kernel(float* __restrict__ rc, float* __restrict__ rs) {
    int idx = blockIdx.x * 256 + threadIdx.x;  // S*32
    int s = idx >> 5, j = idx & 31;
    double inv = exp(-((double)j / 32.0) * 9.210340371976184);
    double ang = (double)s * inv;
    rc[idx] = (float)cos(ang);
    rs[idx] = (float)sin(ang);
}

// ---------------- per-(token,head) RMSNorm + RoPE ----------------
__global__ void rmsrope_kernel(float* __restrict__ qkv,
                               const float* __restrict__ rc,
                               const float* __restrict__ rs) {
    int s = blockIdx.x;
    int warp = threadIdx.x >> 5, lane = threadIdx.x & 31;
    int hh = blockIdx.y * 8 + warp;
    int which = hh >> 4;
    int h = hh & 15;
    float* base = qkv + (size_t)s * 3 * D_MODEL + which * D_MODEL + h * DH;
    float x1 = base[lane], x2 = base[lane + 32];
    float ss = x1 * x1 + x2 * x2;
    #pragma unroll
    for (int off = 16; off; off >>= 1) ss += __shfl_xor_sync(0xffffffff, ss, off);
    float r = rsqrtf(ss * (1.f / DH) + 1e-6f);
    x1 *= r; x2 *= r;
    float c = rc[s * 32 + lane], sn = rs[s * 32 + lane];
    base[lane]      = x1 * c - x2 * sn;
    base[lane + 32] = x1 * sn + x2 * c;
}

// ---------------- frame-masked flash attention, fused bf16 split output ----------------
__global__ void __launch_bounds__(256, 4)
attn_kernel(const float* __restrict__ qkv, __nv_bfloat16* __restrict__ Oa, int window) {
    int f = blockIdx.x;
    int h = blockIdx.y;
    int tid = threadIdx.x;
    int warp = tid >> 5, lane = tid & 31;
    __shared__ float Qs[8][DH];
    __shared__ float Ks[32][DH + 4];
    __shared__ float Vs[32][DH + 2];
    int h0 = h * DH;
    int qrow0 = f * TPF;
    for (int i = tid; i < 8 * DH; i += 256) {
        int r = i >> 6, d = i & 63;
        Qs[r][d] = qkv[(size_t)(qrow0 + r) * 3 * D_MODEL + h0 + d];
    }
    __syncthreads();

    int fstart = max(0, f - window + 1);
    int kstart = fstart * TPF;
    int kend = (f + 1) * TPF;
    int nk = kend - kstart;

    float m = -1e30f, l = 0.f;
    float o0 = 0.f, o1 = 0.f;
    int q = warp;
    int d0 = lane * 2;
    const float sc = 0.125f;

    for (int c0 = 0; c0 < nk; c0 += 32) {
        for (int i = tid; i < 32 * DH; i += 256) {
            int r = i >> 6, d = i & 63;
            int kr = kstart + c0 + r;
            if (kr > S_LEN - 1) kr = S_LEN - 1;
            Ks[r][d] = qkv[(size_t)kr * 3 * D_MODEL + D_MODEL + h0 + d];
            Vs[r][d] = qkv[(size_t)kr * 3 * D_MODEL + 2 * D_MODEL + h0 + d];
        }
        __syncthreads();

        float s;
        if (c0 + lane < nk) {
            float a0 = 0.f, a1 = 0.f, a2 = 0.f, a3 = 0.f;
            #pragma unroll
            for (int d = 0; d < DH; d += 4) {
                a0 = fmaf(Qs[q][d],     Ks[lane][d],     a0);
                a1 = fmaf(Qs[q][d + 1], Ks[lane][d + 1], a1);
                a2 = fmaf(Qs[q][d + 2], Ks[lane][d + 2], a2);
                a3 = fmaf(Qs[q][d + 3], Ks[lane][d + 3], a3);
            }
            s = (a0 + a1 + a2 + a3) * sc;
        } else {
            s = -1e30f;
        }
        float cm = s;
        #pragma unroll
        for (int off = 16; off; off >>= 1) cm = fmaxf(cm, __shfl_xor_sync(0xffffffff, cm, off));
        float mnew = fmaxf(m, cm);
        float p = __expf(s - mnew);
        if (c0 + lane >= nk) p = 0.f;
        float ps = p;
        #pragma unroll
        for (int off = 16; off; off >>= 1) ps += __shfl_xor_sync(0xffffffff, ps, off);
        float factor = __expf(m - mnew);
        l = l * factor + ps;
        m = mnew;
        o0 *= factor; o1 *= factor;
        #pragma unroll
        for (int k = 0; k < 32; k++) {
            float pk = __shfl_sync(0xffffffff, p, k);
            o0 = fmaf(pk, Vs[k][d0],     o0);
            o1 = fmaf(pk, Vs[k][d0 + 1], o1);
        }
        __syncthreads();
    }
    float invl = 1.f / l;
    float a = o0 * invl, b = o1 * invl;
    __nv_bfloat162 hi, lo;
    hi.x = __float2bfloat16(a);
    hi.y = __float2bfloat16(b);
    lo.x = __float2bfloat16(a - __bfloat162float(hi.x));
    lo.y = __float2bfloat16(b - __bfloat162float(hi.y));
    size_t rb = (size_t)(qrow0 + q) * 2 * D_MODEL;
    *(__nv_bfloat162*)(Oa + rb + h0 + d0)           = hi;
    *(__nv_bfloat162*)(Oa + rb + D_MODEL + h0 + d0) = lo;
}

// ---------------- host-side orchestration ----------------
extern "C" void kernel_launch(void* const* d_in, const int* in_sizes, int n_in,
                              void* d_out, int out_size) {
    const float* x       = (const float*)d_in[0];
    const float* cond    = (const float*)d_in[1];
    const float* qkv_w   = (const float*)d_in[2];
    const float* qkv_b   = (const float*)d_in[3];
    const float* out_w   = (const float*)d_in[4];
    const float* out_b   = (const float*)d_in[5];
    const float* mlp_w1  = (const float*)d_in[6];
    const float* mlp_b1  = (const float*)d_in[7];
    const float* mlp_w2  = (const float*)d_in[8];
    const float* mlp_b2  = (const float*)d_in[9];
    const float* ada1_w  = (const float*)d_in[10];
    const float* ada1_b  = (const float*)d_in[11];
    const float* gate1_w = (const float*)d_in[12];
    const float* gate1_b = (const float*)d_in[13];
    const float* ada2_w  = (const float*)d_in[14];
    const float* ada2_b  = (const float*)d_in[15];
    const float* gate2_w = (const float*)d_in[16];
    const float* gate2_b = (const float*)d_in[17];
    float* X = (float*)d_out;

    float *qkv_ptr, *mod_ptr, *rc_ptr, *rs_ptr;
    __nv_bfloat16 *abuf, *abuf2, *wbuf;
    cudaGetSymbolAddress((void**)&qkv_ptr, g_qkv);
    cudaGetSymbolAddress((void**)&mod_ptr, g_mod);
    cudaGetSymbolAddress((void**)&rc_ptr,  g_ropec);
    cudaGetSymbolAddress((void**)&rs_ptr,  g_ropes);
    cudaGetSymbolAddress((void**)&abuf,    g_abuf);
    cudaGetSymbolAddress((void**)&abuf2,   g_abuf2);
    cudaGetSymbolAddress((void**)&wbuf,    g_wbuf);

    // dynamic SMEM: (2*BM*80 + 2*32*272) * 2 stages
    const int SM128 = (2 * 128 * 80 + 2 * 32 * 272) * 2;  // 75776
    const int SM64  = (2 * 64 * 80 + 2 * 32 * 272) * 2;   // 55296
    cudaFuncSetAttribute(mma_gemm<0, 128>, cudaFuncAttributeMaxDynamicSharedMemorySize, SM128);
    cudaFuncSetAttribute(mma_gemm<1, 128>, cudaFuncAttributeMaxDynamicSharedMemorySize, SM128);
    cudaFuncSetAttribute(mma_gemm<2, 64>,  cudaFuncAttributeMaxDynamicSharedMemorySize, SM64);

    cudaMemcpyAsync(X, x, (size_t)S_LEN * D_MODEL * sizeof(float), cudaMemcpyDeviceToDevice);

    rope_table_kernel<<<S_LEN * 32 / 256, 256>>>(rc_ptr, rs_ptr);

    modgate_kernel<<<L_LAYERS * 6 * D_MODEL / 256, 256>>>(
        cond, ada1_w, ada1_b, gate1_w, gate1_b, ada2_w, ada2_b, gate2_w, gate2_b, mod_ptr);

    for (int i = 0; i < L_LAYERS; i++) {
        const float* mod = mod_ptr + i * 6 * D_MODEL;
        int window = (i % 4 == 0) ? 128 : 8;

        // ---- attention block ----
        ln_mod_kernel<<<S_LEN, 256>>>(X, mod, mod + D_MODEL, abuf);

        split_w_kernel<<<dim3(3 * D_MODEL / 1024, D_MODEL), 256>>>(
            qkv_w + (size_t)i * D_MODEL * 3 * D_MODEL, wbuf, D_MODEL, 3 * D_MODEL);
        mma_gemm<0, 128><<<dim3(3 * D_MODEL / 128, S_LEN / 128), 256, SM128>>>(
            abuf, wbuf, qkv_b + i * 3 * D_MODEL, nullptr, qkv_ptr, nullptr, nullptr,
            S_LEN, 3 * D_MODEL, D_MODEL);

        rmsrope_kernel<<<dim3(S_LEN, 4), 256>>>(qkv_ptr, rc_ptr, rs_ptr);
        attn_kernel<<<dim3(NFRAMES, NH), 256>>>(qkv_ptr, abuf, window);

        split_w_kernel<<<dim3(D_MODEL / 1024, D_MODEL), 256>>>(
            out_w + (size_t)i * D_MODEL * D_MODEL, wbuf, D_MODEL, D_MODEL);
        mma_gemm<2, 64><<<dim3(D_MODEL / 128, S_LEN / 64), 256, SM64>>>(
            abuf, wbuf, out_b + i * D_MODEL, mod + 2 * D_MODEL, X, nullptr, X,
            S_LEN, D_MODEL, D_MODEL);

        // ---- MLP block ----
        ln_mod_kernel<<<S_LEN, 256>>>(X, mod + 3 * D_MODEL, mod + 4 * D_MODEL, abuf);

        split_w_kernel<<<dim3(DFF / 1024, D_MODEL), 256>>>(
            mlp_w1 + (size_t)i * D_MODEL * DFF, wbuf, D_MODEL, DFF);
        mma_gemm<1, 128><<<dim3(DFF / 128, S_LEN / 128), 256, SM128>>>(
            abuf, wbuf, mlp_b1 + i * DFF, nullptr, nullptr, abuf2, nullptr,
            S_LEN, DFF, D_MODEL);

        split_w_kernel<<<dim3(D_MODEL / 1024, DFF), 256>>>(
            mlp_w2 + (size_t)i * DFF * D_MODEL, wbuf, DFF, D_MODEL);
        mma_gemm<2, 64><<<dim3(D_MODEL / 128, S_LEN / 64), 256, SM64>>>(
            abuf2, wbuf, mlp_b2 + i * D_MODEL, mod + 5 * D_MODEL, X, nullptr, X,
            S_LEN, D_MODEL, DFF);
    }
}

// round 10
// speedup vs baseline: 3.8262x; 1.0630x over previous
#include <cuda_runtime.h>
#include <cuda_bf16.h>
#include <math.h>
#include <stdint.h>

#define S_LEN 1024
#define D_MODEL 1024
#define NH 16
#define DH 64
#define L_LAYERS 4
#define DFF 4096
#define TPF 8
#define NFRAMES (S_LEN / TPF)

// ---------------- scratch (device globals; no allocation) ----------------
__device__ float g_qkv[S_LEN * 3 * D_MODEL];
__device__ float g_mod[L_LAYERS * 6 * D_MODEL];
__device__ float g_ropec[S_LEN * 32];
__device__ float g_ropes[S_LEN * 32];
__device__ __nv_bfloat16 g_abuf[1024 * 2048];
__device__ __nv_bfloat16 g_abuf2[1024 * 8192];
__device__ __nv_bfloat16 g_wbuf[8192 * 1024];

// ---------------- helpers ----------------
__device__ __forceinline__ uint32_t smem_u32(const void* p) {
    uint32_t a;
    asm("{ .reg .u64 t; cvta.to.shared.u64 t, %1; cvt.u32.u64 %0, t; }" : "=r"(a) : "l"(p));
    return a;
}
#define CP16(dst, src) \
    asm volatile("cp.async.cg.shared.global [%0], [%1], 16;" :: "r"(dst), "l"(src))
#define CP_COMMIT() asm volatile("cp.async.commit_group;")
#define CP_WAIT(n)  asm volatile("cp.async.wait_group %0;" :: "n"(n))
#define LDSM4(r0, r1, r2, r3, addr)                                        \
    asm volatile("ldmatrix.sync.aligned.m8n8.x4.shared.b16 {%0,%1,%2,%3}, [%4];" \
        : "=r"(r0), "=r"(r1), "=r"(r2), "=r"(r3) : "r"(addr))
#define LDSM4T(r0, r1, r2, r3, addr)                                       \
    asm volatile("ldmatrix.sync.aligned.m8n8.x4.trans.shared.b16 {%0,%1,%2,%3}, [%4];" \
        : "=r"(r0), "=r"(r1), "=r"(r2), "=r"(r3) : "r"(addr))
#define MMA(acc, ar, br)                                                   \
    asm volatile(                                                          \
        "mma.sync.aligned.m16n8k16.row.col.f32.bf16.bf16.f32 "             \
        "{%0,%1,%2,%3}, {%4,%5,%6,%7}, {%8,%9}, {%0,%1,%2,%3};"            \
        : "+f"((acc)[0]), "+f"((acc)[1]), "+f"((acc)[2]), "+f"((acc)[3])   \
        : "r"((ar)[0]), "r"((ar)[1]), "r"((ar)[2]), "r"((ar)[3]),          \
          "r"((br)[0]), "r"((br)[1]))

__device__ __forceinline__ float gelu_tanh(float v) {
    float t = tanhf(0.7978845608028654f * (v + 0.044715f * v * v * v));
    return 0.5f * v * (1.f + t);
}

__device__ __forceinline__ void store_split2(__nv_bfloat16* Cs, size_t rowbase, int col,
                                             int N, float a, float b) {
    __nv_bfloat162 hi, lo;
    hi.x = __float2bfloat16(a);
    hi.y = __float2bfloat16(b);
    lo.x = __float2bfloat16(a - __bfloat162float(hi.x));
    lo.y = __float2bfloat16(b - __bfloat162float(hi.y));
    *(__nv_bfloat162*)(Cs + rowbase + col)     = hi;
    *(__nv_bfloat162*)(Cs + rowbase + N + col) = lo;
}

// ---------------- weight split: W [K,N] fp32 -> [2K,N] bf16 (hi rows | lo rows) ----------------
__global__ void split_w_kernel(const float* __restrict__ W, __nv_bfloat16* __restrict__ out,
                               int K, int N) {
    int n0 = blockIdx.x * 1024 + threadIdx.x * 4;
    int k = blockIdx.y;
    float4 w = *(const float4*)(W + (size_t)k * N + n0);
    __nv_bfloat162 h0, h1, l0, l1;
    h0.x = __float2bfloat16(w.x); h0.y = __float2bfloat16(w.y);
    h1.x = __float2bfloat16(w.z); h1.y = __float2bfloat16(w.w);
    l0.x = __float2bfloat16(w.x - __bfloat162float(h0.x));
    l0.y = __float2bfloat16(w.y - __bfloat162float(h0.y));
    l1.x = __float2bfloat16(w.z - __bfloat162float(h1.x));
    l1.y = __float2bfloat16(w.w - __bfloat162float(h1.y));
    uint2 hu, lu;
    hu.x = *(uint32_t*)&h0; hu.y = *(uint32_t*)&h1;
    lu.x = *(uint32_t*)&l0; lu.y = *(uint32_t*)&l1;
    *(uint2*)(out + (size_t)k * N + n0)       = hu;
    *(uint2*)(out + (size_t)(K + k) * N + n0) = lu;
}

// ---------------- mma.sync bf16 3-term GEMM, 3-stage pipeline, 1 sync/chunk ----------------
template <int MODE, int BM>
__global__ void __launch_bounds__(256, 2)
mma_gemm(const __nv_bfloat16* __restrict__ A, const __nv_bfloat16* __restrict__ B,
         const float* __restrict__ bias, const float* __restrict__ gate,
         float* __restrict__ C, __nv_bfloat16* __restrict__ Cs,
         const float* __restrict__ X, int M, int N, int K) {
    constexpr int WARPS_M = BM / 32;
    constexpr int WARPS_N = 8 / WARPS_M;
    constexpr int WTN = 128 / WARPS_N;
    constexpr int NAT = WTN / 8;
    constexpr int ROWA = 80;
    constexpr int ROWB = 272;
    constexpr int OFF_AL = BM * ROWA;
    constexpr int OFF_BH = 2 * BM * ROWA;
    constexpr int STG = 2 * BM * ROWA + 2 * 32 * ROWB;
    constexpr int A_OPS = BM / 64;
    constexpr int B_OPS = 2;

    extern __shared__ __align__(128) char dyn[];
    uint32_t sb = smem_u32(dyn);
    int tid = threadIdx.x;
    int wid = tid >> 5, lane = tid & 31;
    int wm = wid / WARPS_N, wn = wid % WARPS_N;
    int bm = blockIdx.y * BM, bn = blockIdx.x * 128;

    float acc[2][NAT][4];
    #pragma unroll
    for (int i = 0; i < 2; i++)
        #pragma unroll
        for (int j = 0; j < NAT; j++)
            #pragma unroll
            for (int q = 0; q < 4; q++) acc[i][j][q] = 0.f;

    int nch = K >> 5;

    const __nv_bfloat16* srcA[A_OPS];
    uint32_t dA[A_OPS];
    #pragma unroll
    for (int i = 0; i < A_OPS; i++) {
        int idx = tid + i * 256;
        int r = idx >> 2, seg = idx & 3;
        srcA[i] = A + (size_t)(bm + r) * (2 * K) + seg * 8;
        dA[i] = sb + r * ROWA + seg * 16;
    }
    const __nv_bfloat16* srcB[B_OPS];
    uint32_t dB[B_OPS];
    #pragma unroll
    for (int i = 0; i < B_OPS; i++) {
        int idx = tid + i * 256;
        int r = idx >> 4, seg = idx & 15;
        srcB[i] = B + (size_t)r * N + bn + seg * 8;
        dB[i] = sb + OFF_BH + r * ROWB + seg * 16;
    }

    auto issue = [&](int kc, int st) {
        uint32_t so = st * STG;
        #pragma unroll
        for (int i = 0; i < A_OPS; i++) {
            CP16(dA[i] + so, srcA[i] + kc * 32);
            CP16(dA[i] + so + OFF_AL, srcA[i] + K + kc * 32);
        }
        #pragma unroll
        for (int i = 0; i < B_OPS; i++) {
            CP16(dB[i] + so, srcB[i] + (size_t)kc * 32 * N);
            CP16(dB[i] + so + 32 * ROWB, srcB[i] + (size_t)(K + kc * 32) * N);
        }
    };

    // prologue: chunks 0,1 into stages 0,1
    issue(0, 0); CP_COMMIT();
    issue(1, 1); CP_COMMIT();

    int grp = lane >> 3, lr = lane & 7;
    uint32_t aoff[2][2];
    #pragma unroll
    for (int ks = 0; ks < 2; ks++)
        #pragma unroll
        for (int ma = 0; ma < 2; ma++)
            aoff[ks][ma] = (wm * 32 + ma * 16 + (grp & 1) * 8 + lr) * ROWA +
                           (ks * 16 + (grp >> 1) * 8) * 2;
    uint32_t boff[2][NAT / 2];
    #pragma unroll
    for (int ks = 0; ks < 2; ks++)
        #pragma unroll
        for (int p = 0; p < NAT / 2; p++)
            boff[ks][p] = OFF_BH + (ks * 16 + lr + (grp & 1) * 8) * ROWB +
                          (wn * WTN + p * 16 + ((lane >> 4) & 1) * 8) * 2;

    int st_c = 0;       // stage of chunk c
    int st_n = 2;       // stage for chunk c+2
    for (int c = 0; c < nch; c++) {
        CP_WAIT(1);
        __syncthreads();   // chunk c ready; all warps done with stage st_n (was c-1)
        if (c + 2 < nch) issue(c + 2, st_n);
        CP_COMMIT();

        uint32_t base = sb + st_c * STG;
        st_c = (st_c == 2) ? 0 : st_c + 1;
        st_n = (st_n == 2) ? 0 : st_n + 1;

        #pragma unroll
        for (int ks = 0; ks < 2; ks++) {
            uint32_t ah[2][4], al[2][4];
            #pragma unroll
            for (int ma = 0; ma < 2; ma++) {
                LDSM4(ah[ma][0], ah[ma][1], ah[ma][2], ah[ma][3], base + aoff[ks][ma]);
                LDSM4(al[ma][0], al[ma][1], al[ma][2], al[ma][3],
                      base + aoff[ks][ma] + OFF_AL);
            }
            #pragma unroll
            for (int p = 0; p < NAT / 2; p++) {
                uint32_t b0[2], b1[2];
                LDSM4T(b0[0], b0[1], b1[0], b1[1], base + boff[ks][p]);
                #pragma unroll
                for (int ma = 0; ma < 2; ma++) {
                    MMA(acc[ma][2 * p],     ah[ma], b0);
                    MMA(acc[ma][2 * p + 1], ah[ma], b1);
                    MMA(acc[ma][2 * p],     al[ma], b0);
                    MMA(acc[ma][2 * p + 1], al[ma], b1);
                }
            }
            #pragma unroll
            for (int p = 0; p < NAT / 2; p++) {
                uint32_t b0[2], b1[2];
                LDSM4T(b0[0], b0[1], b1[0], b1[1], base + boff[ks][p] + 32 * ROWB);
                #pragma unroll
                for (int ma = 0; ma < 2; ma++) {
                    MMA(acc[ma][2 * p],     ah[ma], b0);
                    MMA(acc[ma][2 * p + 1], ah[ma], b1);
                }
            }
        }
    }

    // epilogue
    int tr = lane >> 2, tc = (lane & 3) * 2;
    #pragma unroll
    for (int ma = 0; ma < 2; ma++) {
        int row = bm + wm * 32 + ma * 16 + tr;
        #pragma unroll
        for (int na = 0; na < NAT; na++) {
            int col = bn + wn * WTN + na * 8 + tc;
            float2 bv = *(const float2*)(bias + col);
            float v0 = acc[ma][na][0] + bv.x;
            float v1 = acc[ma][na][1] + bv.y;
            float v2 = acc[ma][na][2] + bv.x;
            float v3 = acc[ma][na][3] + bv.y;
            if (MODE == 1) {
                v0 = gelu_tanh(v0); v1 = gelu_tanh(v1);
                v2 = gelu_tanh(v2); v3 = gelu_tanh(v3);
                store_split2(Cs, (size_t)row * 2 * N, col, N, v0, v1);
                store_split2(Cs, (size_t)(row + 8) * 2 * N, col, N, v2, v3);
            } else {
                if (MODE == 2) {
                    float2 gv = *(const float2*)(gate + col);
                    float2 x0 = *(const float2*)(X + (size_t)row * N + col);
                    float2 x1 = *(const float2*)(X + (size_t)(row + 8) * N + col);
                    v0 = x0.x + v0 * gv.x; v1 = x0.y + v1 * gv.y;
                    v2 = x1.x + v2 * gv.x; v3 = x1.y + v3 * gv.y;
                }
                *(float2*)(C + (size_t)row * N + col)       = make_float2(v0, v1);
                *(float2*)(C + (size_t)(row + 8) * N + col) = make_float2(v2, v3);
            }
        }
    }
}

// ---------------- mod/gate precompute ----------------
__global__ void modgate_kernel(const float* __restrict__ cond,
                               const float* __restrict__ a1w, const float* __restrict__ a1b,
                               const float* __restrict__ g1w, const float* __restrict__ g1b,
                               const float* __restrict__ a2w, const float* __restrict__ a2b,
                               const float* __restrict__ g2w, const float* __restrict__ g2b,
                               float* __restrict__ out) {
    __shared__ float cs[D_MODEL];
    for (int i = threadIdx.x; i < D_MODEL; i += blockDim.x) cs[i] = cond[i];
    __syncthreads();
    int o = blockIdx.x * blockDim.x + threadIdx.x;
    int l = o / (6 * D_MODEL);
    int j = o % (6 * D_MODEL);
    const float* W; const float* Bv; int col, ncols;
    if (j < 2 * D_MODEL)      { W = a1w + (size_t)l * D_MODEL * 2 * D_MODEL; Bv = a1b + l * 2 * D_MODEL; col = j;               ncols = 2 * D_MODEL; }
    else if (j < 3 * D_MODEL) { W = g1w + (size_t)l * D_MODEL * D_MODEL;     Bv = g1b + l * D_MODEL;     col = j - 2 * D_MODEL; ncols = D_MODEL; }
    else if (j < 5 * D_MODEL) { W = a2w + (size_t)l * D_MODEL * 2 * D_MODEL; Bv = a2b + l * 2 * D_MODEL; col = j - 3 * D_MODEL; ncols = 2 * D_MODEL; }
    else                      { W = g2w + (size_t)l * D_MODEL * D_MODEL;     Bv = g2b + l * D_MODEL;     col = j - 5 * D_MODEL; ncols = D_MODEL; }
    float acc = 0.f;
    #pragma unroll 8
    for (int d = 0; d < D_MODEL; d++) acc += cs[d] * W[(size_t)d * ncols + col];
    out[o] = acc + Bv[col];
}

// ---------------- LayerNorm + adaLN modulation, fused bf16 split out ----------------
__global__ void ln_mod_kernel(const float* __restrict__ x,
                              const float* __restrict__ shift,
                              const float* __restrict__ scale,
                              __nv_bfloat16* __restrict__ out) {
    int row = blockIdx.x;
    int tid = threadIdx.x;
    const float* xr = x + (size_t)row * D_MODEL;
    float v[4], s = 0.f, s2 = 0.f;
    #pragma unroll
    for (int i = 0; i < 4; i++) {
        v[i] = xr[tid + i * 256];
        s += v[i]; s2 += v[i] * v[i];
    }
    #pragma unroll
    for (int off = 16; off; off >>= 1) {
        s  += __shfl_xor_sync(0xffffffff, s,  off);
        s2 += __shfl_xor_sync(0xffffffff, s2, off);
    }
    __shared__ float sh1[8], sh2[8];
    int w = tid >> 5, lane = tid & 31;
    if (lane == 0) { sh1[w] = s; sh2[w] = s2; }
    __syncthreads();
    if (tid == 0) {
        float a = 0.f, b = 0.f;
        #pragma unroll
        for (int i = 0; i < 8; i++) { a += sh1[i]; b += sh2[i]; }
        sh1[0] = a; sh2[0] = b;
    }
    __syncthreads();
    float mean = sh1[0] * (1.f / D_MODEL);
    float var  = sh2[0] * (1.f / D_MODEL) - mean * mean;
    float r = rsqrtf(var + 1e-5f);
    __nv_bfloat16* orow = out + (size_t)row * 2 * D_MODEL;
    #pragma unroll
    for (int i = 0; i < 4; i++) {
        int col = tid + i * 256;
        float hv = (v[i] - mean) * r * (1.f + scale[col]) + shift[col];
        __nv_bfloat16 hi = __float2bfloat16(hv);
        orow[col]           = hi;
        orow[D_MODEL + col] = __float2bfloat16(hv - __bfloat162float(hi));
    }
}

// ---------------- RoPE table (fp64 once) ----------------
__global__ void rope_table_kernel(float* __restrict__ rc, float* __restrict__ rs) {
    int idx = blockIdx.x * 256 + threadIdx.x;
    int s = idx >> 5, j = idx & 31;
    double inv = exp(-((double)j / 32.0) * 9.210340371976184);
    double ang = (double)s * inv;
    rc[idx] = (float)cos(ang);
    rs[idx] = (float)sin(ang);
}

// ---------------- per-(token,head) RMSNorm + RoPE ----------------
__global__ void rmsrope_kernel(float* __restrict__ qkv,
                               const float* __restrict__ rc,
                               const float* __restrict__ rs) {
    int s = blockIdx.x;
    int warp = threadIdx.x >> 5, lane = threadIdx.x & 31;
    int hh = blockIdx.y * 8 + warp;
    int which = hh >> 4;
    int h = hh & 15;
    float* base = qkv + (size_t)s * 3 * D_MODEL + which * D_MODEL + h * DH;
    float x1 = base[lane], x2 = base[lane + 32];
    float ss = x1 * x1 + x2 * x2;
    #pragma unroll
    for (int off = 16; off; off >>= 1) ss += __shfl_xor_sync(0xffffffff, ss, off);
    float r = rsqrtf(ss * (1.f / DH) + 1e-6f);
    x1 *= r; x2 *= r;
    float c = rc[s * 32 + lane], sn = rs[s * 32 + lane];
    base[lane]      = x1 * c - x2 * sn;
    base[lane + 32] = x1 * sn + x2 * c;
}

// ---------------- frame-masked flash attention, fused bf16 split output ----------------
__global__ void __launch_bounds__(256, 4)
attn_kernel(const float* __restrict__ qkv, __nv_bfloat16* __restrict__ Oa, int window) {
    int f = blockIdx.x;
    int h = blockIdx.y;
    int tid = threadIdx.x;
    int warp = tid >> 5, lane = tid & 31;
    __shared__ float Qs[8][DH];
    __shared__ float Ks[32][DH + 4];
    __shared__ float Vs[32][DH + 2];
    int h0 = h * DH;
    int qrow0 = f * TPF;
    for (int i = tid; i < 8 * DH; i += 256) {
        int r = i >> 6, d = i & 63;
        Qs[r][d] = qkv[(size_t)(qrow0 + r) * 3 * D_MODEL + h0 + d];
    }
    __syncthreads();

    int fstart = max(0, f - window + 1);
    int kstart = fstart * TPF;
    int kend = (f + 1) * TPF;
    int nk = kend - kstart;

    float m = -1e30f, l = 0.f;
    float o0 = 0.f, o1 = 0.f;
    int q = warp;
    int d0 = lane * 2;
    const float sc = 0.125f;

    for (int c0 = 0; c0 < nk; c0 += 32) {
        for (int i = tid; i < 32 * DH; i += 256) {
            int r = i >> 6, d = i & 63;
            int kr = kstart + c0 + r;
            if (kr > S_LEN - 1) kr = S_LEN - 1;
            Ks[r][d] = qkv[(size_t)kr * 3 * D_MODEL + D_MODEL + h0 + d];
            Vs[r][d] = qkv[(size_t)kr * 3 * D_MODEL + 2 * D_MODEL + h0 + d];
        }
        __syncthreads();

        float s;
        if (c0 + lane < nk) {
            float a0 = 0.f, a1 = 0.f, a2 = 0.f, a3 = 0.f;
            #pragma unroll
            for (int d = 0; d < DH; d += 4) {
                a0 = fmaf(Qs[q][d],     Ks[lane][d],     a0);
                a1 = fmaf(Qs[q][d + 1], Ks[lane][d + 1], a1);
                a2 = fmaf(Qs[q][d + 2], Ks[lane][d + 2], a2);
                a3 = fmaf(Qs[q][d + 3], Ks[lane][d + 3], a3);
            }
            s = (a0 + a1 + a2 + a3) * sc;
        } else {
            s = -1e30f;
        }
        float cm = s;
        #pragma unroll
        for (int off = 16; off; off >>= 1) cm = fmaxf(cm, __shfl_xor_sync(0xffffffff, cm, off));
        float mnew = fmaxf(m, cm);
        float p = __expf(s - mnew);
        if (c0 + lane >= nk) p = 0.f;
        float ps = p;
        #pragma unroll
        for (int off = 16; off; off >>= 1) ps += __shfl_xor_sync(0xffffffff, ps, off);
        float factor = __expf(m - mnew);
        l = l * factor + ps;
        m = mnew;
        o0 *= factor; o1 *= factor;
        #pragma unroll
        for (int k = 0; k < 32; k++) {
            float pk = __shfl_sync(0xffffffff, p, k);
            o0 = fmaf(pk, Vs[k][d0],     o0);
            o1 = fmaf(pk, Vs[k][d0 + 1], o1);
        }
        __syncthreads();
    }
    float invl = 1.f / l;
    float a = o0 * invl, b = o1 * invl;
    __nv_bfloat162 hi, lo;
    hi.x = __float2bfloat16(a);
    hi.y = __float2bfloat16(b);
    lo.x = __float2bfloat16(a - __bfloat162float(hi.x));
    lo.y = __float2bfloat16(b - __bfloat162float(hi.y));
    size_t rb = (size_t)(qrow0 + q) * 2 * D_MODEL;
    *(__nv_bfloat162*)(Oa + rb + h0 + d0)           = hi;
    *(__nv_bfloat162*)(Oa + rb + D_MODEL + h0 + d0) = lo;
}

// ---------------- host-side orchestration ----------------
extern "C" void kernel_launch(void* const* d_in, const int* in_sizes, int n_in,
                              void* d_out, int out_size) {
    const float* x       = (const float*)d_in[0];
    const float* cond    = (const float*)d_in[1];
    const float* qkv_w   = (const float*)d_in[2];
    const float* qkv_b   = (const float*)d_in[3];
    const float* out_w   = (const float*)d_in[4];
    const float* out_b   = (const float*)d_in[5];
    const float* mlp_w1  = (const float*)d_in[6];
    const float* mlp_b1  = (const float*)d_in[7];
    const float* mlp_w2  = (const float*)d_in[8];
    const float* mlp_b2  = (const float*)d_in[9];
    const float* ada1_w  = (const float*)d_in[10];
    const float* ada1_b  = (const float*)d_in[11];
    const float* gate1_w = (const float*)d_in[12];
    const float* gate1_b = (const float*)d_in[13];
    const float* ada2_w  = (const float*)d_in[14];
    const float* ada2_b  = (const float*)d_in[15];
    const float* gate2_w = (const float*)d_in[16];
    const float* gate2_b = (const float*)d_in[17];
    float* X = (float*)d_out;

    float *qkv_ptr, *mod_ptr, *rc_ptr, *rs_ptr;
    __nv_bfloat16 *abuf, *abuf2, *wbuf;
    cudaGetSymbolAddress((void**)&qkv_ptr, g_qkv);
    cudaGetSymbolAddress((void**)&mod_ptr, g_mod);
    cudaGetSymbolAddress((void**)&rc_ptr,  g_ropec);
    cudaGetSymbolAddress((void**)&rs_ptr,  g_ropes);
    cudaGetSymbolAddress((void**)&abuf,    g_abuf);
    cudaGetSymbolAddress((void**)&abuf2,   g_abuf2);
    cudaGetSymbolAddress((void**)&wbuf,    g_wbuf);

    // dynamic SMEM: (2*BM*80 + 2*32*272) * 3 stages
    const int SM128 = (2 * 128 * 80 + 2 * 32 * 272) * 3;  // 113664
    const int SM64  = (2 * 64 * 80 + 2 * 32 * 272) * 3;   // 82944
    cudaFuncSetAttribute(mma_gemm<0, 128>, cudaFuncAttributeMaxDynamicSharedMemorySize, SM128);
    cudaFuncSetAttribute(mma_gemm<1, 128>, cudaFuncAttributeMaxDynamicSharedMemorySize, SM128);
    cudaFuncSetAttribute(mma_gemm<2, 64>,  cudaFuncAttributeMaxDynamicSharedMemorySize, SM64);

    cudaMemcpyAsync(X, x, (size_t)S_LEN * D_MODEL * sizeof(float), cudaMemcpyDeviceToDevice);

    rope_table_kernel<<<S_LEN * 32 / 256, 256>>>(rc_ptr, rs_ptr);

    modgate_kernel<<<L_LAYERS * 6 * D_MODEL / 256, 256>>>(
        cond, ada1_w, ada1_b, gate1_w, gate1_b, ada2_w, ada2_b, gate2_w, gate2_b, mod_ptr);

    for (int i = 0; i < L_LAYERS; i++) {
        const float* mod = mod_ptr + i * 6 * D_MODEL;
        int window = (i % 4 == 0) ? 128 : 8;

        // ---- attention block ----
        ln_mod_kernel<<<S_LEN, 256>>>(X, mod, mod + D_MODEL, abuf);

        split_w_kernel<<<dim3(3 * D_MODEL / 1024, D_MODEL), 256>>>(
            qkv_w + (size_t)i * D_MODEL * 3 * D_MODEL, wbuf, D_MODEL, 3 * D_MODEL);
        mma_gemm<0, 128><<<dim3(3 * D_MODEL / 128, S_LEN / 128), 256, SM128>>>(
            abuf, wbuf, qkv_b + i * 3 * D_MODEL, nullptr, qkv_ptr, nullptr, nullptr,
            S_LEN, 3 * D_MODEL, D_MODEL);

        rmsrope_kernel<<<dim3(S_LEN, 4), 256>>>(qkv_ptr, rc_ptr, rs_ptr);
        attn_kernel<<<dim3(NFRAMES, NH), 256>>>(qkv_ptr, abuf, window);

        split_w_kernel<<<dim3(D_MODEL / 1024, D_MODEL), 256>>>(
            out_w + (size_t)i * D_MODEL * D_MODEL, wbuf, D_MODEL, D_MODEL);
        mma_gemm<2, 64><<<dim3(D_MODEL / 128, S_LEN / 64), 256, SM64>>>(
            abuf, wbuf, out_b + i * D_MODEL, mod + 2 * D_MODEL, X, nullptr, X,
            S_LEN, D_MODEL, D_MODEL);

        // ---- MLP block ----
        ln_mod_kernel<<<S_LEN, 256>>>(X, mod + 3 * D_MODEL, mod + 4 * D_MODEL, abuf);

        split_w_kernel<<<dim3(DFF / 1024, D_MODEL), 256>>>(
            mlp_w1 + (size_t)i * D_MODEL * DFF, wbuf, D_MODEL, DFF);
        mma_gemm<1, 128><<<dim3(DFF / 128, S_LEN / 128), 256, SM128>>>(
            abuf, wbuf, mlp_b1 + i * DFF, nullptr, nullptr, abuf2, nullptr,
            S_LEN, DFF, D_MODEL);

        split_w_kernel<<<dim3(D_MODEL / 1024, DFF), 256>>>(
            mlp_w2 + (size_t)i * DFF * D_MODEL, wbuf, DFF, D_MODEL);
        mma_gemm<2, 64><<<dim3(D_MODEL / 128, S_LEN / 64), 256, SM64>>>(
            abuf2, wbuf, mlp_b2 + i * D_MODEL, mod + 5 * D_MODEL, X, nullptr, X,
            S_LEN, D_MODEL, DFF);
    }
}